// round 12
// baseline (speedup 1.0000x reference)
#include <cuda_runtime.h>
#include <math.h>
#include <stdint.h>

#define BATCH 4
#define NTOK 16384
#define CDIM 210
#define C3   630
#define HDIM 35
#define MTOK 128
#define DRED 20
#define DTD 96
#define MLPH 420
#define HF2C 516
#define ROWS (BATCH*NTOK)
#define LOGM 4.852030263919617f

__device__ float g_xn  [ROWS*CDIM];
__device__ float g_qkv [(size_t)ROWS*C3];
__device__ float g_x2  [ROWS*CDIM];
__device__ float g_xn2 [ROWS*CDIM];
__device__ float g_q   [ROWS*DRED];
__device__ float g_kn  [BATCH*MTOK*DRED];
__device__ float g_v   [BATCH*MTOK*CDIM];
__device__ float g_ftd [BATCH*MTOK*DTD];
__device__ int   g_tkid[ROWS];
__device__ int   g_sidx[ROWS];
__device__ float g_aca [ROWS*CDIM];
__device__ float g_win [ROWS*CDIM];
__device__ float g_biasf[6*65536];
__device__ float g_hcat [(size_t)ROWS*HF2C];
__device__ float g_hcat2[(size_t)ROWS*HF2C];

__device__ __forceinline__ float gelu_exact(float v){
    return 0.5f*v*(1.0f+erff(v*0.7071067811865476f));
}

// ---------- LayerNorm: warp per row ----------
__global__ void ln_kernel(const float* __restrict__ in, const float* __restrict__ gam,
                          const float* __restrict__ bet, float* __restrict__ out, int rows)
{
    int warp = (blockIdx.x*blockDim.x + threadIdx.x) >> 5;
    int lane = threadIdx.x & 31;
    if (warp >= rows) return;
    const float* r = in + (size_t)warp*CDIM;
    float v[7]; float s = 0.f;
#pragma unroll
    for (int j=0;j<7;j++){ int k = lane + 32*j; v[j] = (k<CDIM)? r[k] : 0.f; s += v[j]; }
#pragma unroll
    for (int o=16;o;o>>=1) s += __shfl_xor_sync(0xffffffffu, s, o);
    float mu = s * (1.0f/CDIM);
    float vs = 0.f;
#pragma unroll
    for (int j=0;j<7;j++){ int k = lane + 32*j; if (k<CDIM){ float d = v[j]-mu; vs += d*d; } }
#pragma unroll
    for (int o=16;o;o>>=1) vs += __shfl_xor_sync(0xffffffffu, vs, o);
    float rstd = rsqrtf(vs*(1.0f/CDIM) + 1e-5f);
    float* o2 = out + (size_t)warp*CDIM;
#pragma unroll
    for (int j=0;j<7;j++){ int k = lane + 32*j; if (k<CDIM) o2[k] = (v[j]-mu)*rstd*gam[k] + bet[k]; }
}

// ---------- SGEMM: cp.async 4-stage pipeline, 128x128x8, 8x8/thread ----------
__global__ __launch_bounds__(256,2) void sgemm_kernel(
        const float* __restrict__ A, int lda,
        const float* __restrict__ W, int ldw,
        const float* __restrict__ bias,
        const float* __restrict__ addp, int ldadd,
        float* __restrict__ C, int ldc,
        int Mr, int Nc, int K, int act)
{
    __shared__ float As[4][8][128];
    __shared__ float Bs[4][8][128];
    int tid = threadIdx.x;
    int tx = tid & 15, ty = tid >> 4;
    int row0 = blockIdx.y * 128, col0 = blockIdx.x * 128;
    float acc[8][8];
#pragma unroll
    for (int i=0;i<8;i++)
#pragma unroll
        for (int j=0;j<8;j++) acc[i][j]=0.f;
    int nk = (K+7)/8;

    uint32_t aS = (uint32_t)__cvta_generic_to_shared(&As[0][0][0]);
    uint32_t bS = (uint32_t)__cvta_generic_to_shared(&Bs[0][0][0]);

#define SG_ISSUE(kt) do{ \
        int stage = (kt)&3; int k0 = (kt)*8; \
        uint32_t ab = aS + stage*4096, bb = bS + stage*4096; \
        _Pragma("unroll") \
        for (int i_=0;i_<4;i_++){ \
            int f = tid + i_*256; \
            int r = f>>3, kk = f&7; \
            int gr = row0+r, gk = k0+kk; \
            int szA = (gr<Mr && gk<K)?4:0; \
            const float* sa = A + (size_t)(szA?gr:0)*lda + (szA?gk:0); \
            uint32_t da = ab + (uint32_t)((kk*128 + r)*4); \
            asm volatile("cp.async.ca.shared.global [%0], [%1], 4, %2;" :: "r"(da), "l"(sa), "r"(szA)); \
            int kb = f>>7, cb = f&127; \
            int gkb = k0+kb, gc = col0+cb; \
            int szB = (gkb<K && gc<Nc)?4:0; \
            const float* sb = W + (size_t)(szB?gkb:0)*ldw + (szB?gc:0); \
            uint32_t db = bb + (uint32_t)((kb*128 + cb)*4); \
            asm volatile("cp.async.ca.shared.global [%0], [%1], 4, %2;" :: "r"(db), "l"(sb), "r"(szB)); \
        } \
        asm volatile("cp.async.commit_group;"); \
    }while(0)

    int pre = (nk<3)? nk:3;
    for (int s=0;s<pre;s++) SG_ISSUE(s);
    for (int s=pre;s<3;s++) asm volatile("cp.async.commit_group;");

    for (int kt=0; kt<nk; kt++){
        asm volatile("cp.async.wait_group 2;");
        __syncthreads();
        if (kt+3 < nk) SG_ISSUE(kt+3);
        else asm volatile("cp.async.commit_group;");
        int cur = kt&3;
#pragma unroll
        for (int kk=0;kk<8;kk++){
            float4 a0 = *(const float4*)&As[cur][kk][ty*8];
            float4 a1 = *(const float4*)&As[cur][kk][ty*8+4];
            float4 b0 = *(const float4*)&Bs[cur][kk][tx*8];
            float4 b1 = *(const float4*)&Bs[cur][kk][tx*8+4];
            float av[8] = {a0.x,a0.y,a0.z,a0.w,a1.x,a1.y,a1.z,a1.w};
            float bv[8] = {b0.x,b0.y,b0.z,b0.w,b1.x,b1.y,b1.z,b1.w};
#pragma unroll
            for (int i=0;i<8;i++)
#pragma unroll
                for (int j=0;j<8;j++) acc[i][j] += av[i]*bv[j];
        }
    }
#pragma unroll
    for (int i=0;i<8;i++){
        int r = row0 + ty*8 + i;
        if (r >= Mr) continue;
#pragma unroll
        for (int j=0;j<8;j++){
            int c = col0 + tx*8 + j;
            if (c >= Nc) continue;
            float v = acc[i][j] + bias[c];
            if (act==1) v = gelu_exact(v);
            if (addp) v += addp[(size_t)r*ldadd + c];
            C[(size_t)r*ldc + c] = v;
        }
    }
}

// ---------- fused dual-projection GEMM: x2 += aca@W1 + win@W2 + b1 + b2 ----------
__global__ __launch_bounds__(256,2) void sgemm_dual(
        const float* __restrict__ A1, const float* __restrict__ A2,
        const float* __restrict__ W1, const float* __restrict__ W2,
        const float* __restrict__ b1v, const float* __restrict__ b2v,
        float* __restrict__ C)
{
    __shared__ float As[2][8][128];
    __shared__ float Bs[2][8][128];
    int tid = threadIdx.x;
    int tx = tid & 15, ty = tid >> 4;
    int row0 = blockIdx.y * 128, col0 = blockIdx.x * 128;
    float acc[8][8];
#pragma unroll
    for (int i=0;i<8;i++)
#pragma unroll
        for (int j=0;j<8;j++) acc[i][j]=0.f;
    const int K = 420, Nc = 210;
    int nk = (K+7)/8;
    float ra[4], rb[4];
    {
#pragma unroll
        for (int i=0;i<4;i++){
            int f = tid + i*256;
            int r = row0 + (f>>3), kk = f&7;
            ra[i] = A1[(size_t)r*210 + kk];
            int kb = f>>7, cb = f&127;
            int gc = col0+cb;
            rb[i] = (gc<Nc)? W1[kb*210 + gc] : 0.f;
        }
#pragma unroll
        for (int i=0;i<4;i++){
            int f = tid + i*256;
            As[0][f&7][f>>3] = ra[i];
            Bs[0][f>>7][f&127] = rb[i];
        }
    }
    __syncthreads();
    for (int kt=0; kt<nk; kt++){
        int cur = kt&1;
        if (kt+1 < nk){
            int k0 = (kt+1)*8;
#pragma unroll
            for (int i=0;i<4;i++){
                int f = tid + i*256;
                int r = row0 + (f>>3), gk = k0 + (f&7);
                float a = 0.f;
                if (gk < 210)       a = A1[(size_t)r*210 + gk];
                else if (gk < 420)  a = A2[(size_t)r*210 + gk-210];
                ra[i] = a;
                int gkb = k0 + (f>>7), cb = f&127;
                int gc = col0+cb;
                float b = 0.f;
                if (gc < Nc){
                    if (gkb < 210)      b = W1[gkb*210 + gc];
                    else if (gkb < 420) b = W2[(gkb-210)*210 + gc];
                }
                rb[i] = b;
            }
        }
#pragma unroll
        for (int kk=0;kk<8;kk++){
            float4 a0 = *(const float4*)&As[cur][kk][ty*8];
            float4 a1 = *(const float4*)&As[cur][kk][ty*8+4];
            float4 b0 = *(const float4*)&Bs[cur][kk][tx*8];
            float4 b1 = *(const float4*)&Bs[cur][kk][tx*8+4];
            float av[8] = {a0.x,a0.y,a0.z,a0.w,a1.x,a1.y,a1.z,a1.w};
            float bv[8] = {b0.x,b0.y,b0.z,b0.w,b1.x,b1.y,b1.z,b1.w};
#pragma unroll
            for (int i=0;i<8;i++)
#pragma unroll
                for (int j=0;j<8;j++) acc[i][j] += av[i]*bv[j];
        }
        if (kt+1 < nk){
            int nxt = cur^1;
#pragma unroll
            for (int i=0;i<4;i++){
                int f = tid + i*256;
                As[nxt][f&7][f>>3] = ra[i];
                Bs[nxt][f>>7][f&127] = rb[i];
            }
            __syncthreads();
        }
    }
#pragma unroll
    for (int i=0;i<8;i++){
        int r = row0 + ty*8 + i;
#pragma unroll
        for (int j=0;j<8;j++){
            int c = col0 + tx*8 + j;
            if (c >= Nc) continue;
            size_t idx = (size_t)r*210 + c;
            C[idx] = C[idx] + acc[i][j] + b1v[c] + b2v[c];
        }
    }
}

// ---------- q projection + l2norm: warp per row ----------
__global__ void qproj_kernel(const float* __restrict__ wq, const float* __restrict__ bq)
{
    __shared__ float s[4][CDIM];
    int w = threadIdx.x>>5, lane = threadIdx.x&31;
    int row = blockIdx.x*4 + w;
    const float* r = g_xn + (size_t)row*CDIM;
    for (int k=lane;k<CDIM;k+=32) s[w][k] = r[k];
    __syncwarp();
    float acc = 0.f;
    if (lane < DRED){
        acc = bq[lane];
        for (int k=0;k<CDIM;k++) acc += s[w][k]*wq[k*DRED+lane];
    }
    float sq = (lane<DRED)? acc*acc : 0.f;
#pragma unroll
    for (int o=16;o;o>>=1) sq += __shfl_xor_sync(0xffffffffu, sq, o);
    float den = fmaxf(sqrtf(sq), 1e-12f);
    if (lane < DRED) g_q[(size_t)row*DRED + lane] = acc/den;
}

// ---------- td projections ----------
__global__ void kv_kernel(const float* __restrict__ td,
                          const float* __restrict__ wk_w, const float* __restrict__ wk_b,
                          const float* __restrict__ wv_w, const float* __restrict__ wv_b,
                          const float* __restrict__ ftd_w, const float* __restrict__ ftd_b)
{
    __shared__ float tr[CDIM];
    __shared__ float ks_s[DRED];
    __shared__ float nrm_s;
    int rm = blockIdx.x;
    int b = rm >> 7, m = rm & 127;
    int t = threadIdx.x;
    const float* trow = td + (size_t)rm*CDIM;
    if (t < CDIM) tr[t] = trow[t];
    __syncthreads();
    if (t < CDIM){
        float a = wv_b[t];
        for (int k=0;k<CDIM;k++) a += tr[k]*wv_w[k*CDIM+t];
        g_v[(size_t)rm*CDIM + t] = a;
    }
    if (t < DTD){
        float a = ftd_b[t];
        for (int k=0;k<CDIM;k++) a += tr[k]*ftd_w[k*DTD+t];
        g_ftd[(size_t)rm*DTD + t] = a;
    }
    if (t < DRED){
        float a = wk_b[t];
        for (int k=0;k<CDIM;k++) a += tr[k]*wk_w[k*DRED+t];
        ks_s[t] = a;
    }
    __syncthreads();
    if (t==0){
        float s=0.f;
        for (int j=0;j<DRED;j++) s += ks_s[j]*ks_s[j];
        nrm_s = fmaxf(sqrtf(s), 1e-12f);
    }
    __syncthreads();
    if (t < DRED) g_kn[b*(MTOK*DRED) + t*MTOK + m] = ks_s[t]/nrm_s;
}

// ---------- fused ATD cross-attn (4 tokens/warp-iter) ----------
__global__ void atd_kernel(const float* __restrict__ x, const float* __restrict__ atd_scale)
{
    extern __shared__ float sm2[];
    float* vs  = sm2;
    float* knT = vs + MTOK*CDIM;
    float* pbuf= knT + DRED*MTOK;
    int tid = threadIdx.x, wid = tid>>5, lane = tid&31;
    int b  = blockIdx.x >> 8;
    int n0 = (blockIdx.x & 255) * 64;
    for (int f=tid; f<MTOK*CDIM; f+=256) vs[f]  = g_v [b*(MTOK*CDIM)+f];
    for (int f=tid; f<DRED*MTOK; f+=256) knT[f] = g_kn[b*(MTOK*DRED)+f];
    float sc = atd_scale[0];
    sc = 1.0f + fminf(fmaxf(sc,0.0f),3.0f)*LOGM;
    __syncthreads();
    for (int g=0; g<2; g++){
        int n = n0 + wid*8 + g*4;
        size_t rbase = (size_t)b*NTOK + n;
        float ql[4];
#pragma unroll
        for (int i=0;i<4;i++)
            ql[i] = (lane<DRED)? g_q[(rbase+i)*DRED + lane] : 0.f;
        float lg[4][4];
#pragma unroll
        for (int i=0;i<4;i++)
#pragma unroll
            for (int mm=0;mm<4;mm++) lg[i][mm]=0.f;
        for (int j=0;j<DRED;j++){
            float kv[4];
#pragma unroll
            for (int mm=0;mm<4;mm++) kv[mm] = knT[j*MTOK + lane + 32*mm];
#pragma unroll
            for (int i=0;i<4;i++){
                float qv = __shfl_sync(0xffffffffu, ql[i], j);
#pragma unroll
                for (int mm=0;mm<4;mm++) lg[i][mm] += qv*kv[mm];
            }
        }
#pragma unroll
        for (int i=0;i<4;i++){
#pragma unroll
            for (int mm=0;mm<4;mm++) lg[i][mm] *= sc;
            float bv = lg[i][0]; int bi = lane;
#pragma unroll
            for (int mm=1;mm<4;mm++){
                int m = lane+32*mm;
                if (lg[i][mm] > bv){ bv = lg[i][mm]; bi = m; }
            }
#pragma unroll
            for (int o=16;o;o>>=1){
                float ov = __shfl_xor_sync(0xffffffffu, bv, o);
                int   oi = __shfl_xor_sync(0xffffffffu, bi, o);
                if (ov > bv || (ov==bv && oi<bi)){ bv = ov; bi = oi; }
            }
            float sum = 0.f;
#pragma unroll
            for (int mm=0;mm<4;mm++){ lg[i][mm] = expf(lg[i][mm]-bv); sum += lg[i][mm]; }
#pragma unroll
            for (int o=16;o;o>>=1) sum += __shfl_xor_sync(0xffffffffu, sum, o);
            float inv = 1.0f/sum;
#pragma unroll
            for (int mm=0;mm<4;mm++) pbuf[(wid*4+i)*MTOK + lane + 32*mm] = lg[i][mm]*inv;
            if (lane==0) g_tkid[rbase+i] = bi;
        }
        __syncwarp();
        float a[4][7];
#pragma unroll
        for (int i=0;i<4;i++)
#pragma unroll
            for (int k=0;k<7;k++) a[i][k]=0.f;
#pragma unroll 2
        for (int m=0;m<MTOK;m++){
            float vv[7];
            const float* vrow = vs + m*CDIM;
#pragma unroll
            for (int k=0;k<6;k++) vv[k] = vrow[lane+32*k];
            vv[6] = (lane<18)? vrow[lane+192] : 0.f;
#pragma unroll
            for (int i=0;i<4;i++){
                float pm = pbuf[(wid*4+i)*MTOK + m];
#pragma unroll
                for (int k=0;k<7;k++) a[i][k] += pm*vv[k];
            }
        }
#pragma unroll
        for (int i=0;i<4;i++){
            const float* xr = x + (rbase+i)*CDIM;
            float* orow = g_x2 + (rbase+i)*CDIM;
#pragma unroll
            for (int k=0;k<6;k++) orow[lane+32*k] = xr[lane+32*k] + a[i][k];
            if (lane<18) orow[lane+192] = xr[lane+192] + a[i][6];
        }
        __syncwarp();
    }
}

// ---------- stable counting sort per batch ----------
__global__ void sort_kernel()
{
    __shared__ int cnt[64*128];
    __shared__ int binbase[128];
    int b = blockIdx.x, t = threadIdx.x;
    const int* key = g_tkid + b*NTOK;
    int* out = g_sidx + b*NTOK;
    for (int i=t;i<64*128;i+=64) cnt[i]=0;
    __syncthreads();
    for (int i=0;i<256;i++){ int k = key[t*256+i]; cnt[t*128+k]++; }
    __syncthreads();
    for (int bb=t; bb<128; bb+=64){
        int tot=0;
        for (int th=0; th<64; th++){ int v = cnt[th*128+bb]; cnt[th*128+bb]=tot; tot+=v; }
        binbase[bb]=tot;
    }
    __syncthreads();
    if (t==0){ int s=0; for (int bn=0;bn<128;bn++){ int v=binbase[bn]; binbase[bn]=s; s+=v; } }
    __syncthreads();
    for (int i=0;i<256;i++){
        int tok = t*256+i;
        int k = key[tok];
        int pos = binbase[k] + cnt[t*128+k]++;
        out[pos] = tok;
    }
}

// ---------- window bias precompute ----------
__global__ void biasprep_kernel(const float* __restrict__ rpb, const int* __restrict__ rpi)
{
    int i = blockIdx.x*256 + threadIdx.x;
    int r = rpi[i];
#pragma unroll
    for (int h=0;h<6;h++) g_biasf[h*65536 + i] = rpb[r*6 + h];
}

// ---------- attention core (stride 260, float4 PV) ----------
#define KSTR 260
#define ATT_SMEM ((2*35*KSTR + 8*4*256 + 256)*4)

__global__ __launch_bounds__(256,2) void acmsa_kernel()
{
    extern __shared__ float sm[];
    float* kT = sm;
    float* vT = sm + 35*KSTR;
    float* ps = sm + 2*35*KSTR;
    int*  tok = (int*)(sm + 2*35*KSTR + 8*4*256);
    int head = blockIdx.x, grp = blockIdx.y, b = blockIdx.z;
    int tid = threadIdx.x, wid = tid>>5, lane = tid&31;
    tok[tid] = g_sidx[b*NTOK + grp*256 + tid];
    __syncthreads();
    const float* qb = g_qkv + (size_t)b*NTOK*C3;
    for (int i=wid; i<256; i+=8){
        const float* p = qb + (size_t)tok[i]*C3 + head*HDIM;
        kT[lane*KSTR+i] = p[CDIM + lane];
        vT[lane*KSTR+i] = p[2*CDIM + lane];
        if (lane<3){
            kT[(lane+32)*KSTR+i] = p[CDIM + lane+32];
            vT[(lane+32)*KSTR+i] = p[2*CDIM + lane+32];
        }
    }
    __syncthreads();
    const float rs = 0.16903085094570331f;
    for (int it=0; it<8; it++){
        int qi0 = wid*32 + it*4;
        int tq[4]; float qd[4], qd2[4];
#pragma unroll
        for (int i=0;i<4;i++){
            tq[i] = tok[qi0+i];
            const float* qp = qb + (size_t)tq[i]*C3 + head*HDIM;
            qd[i]  = qp[lane];
            qd2[i] = (lane<3)? qp[lane+32] : 0.f;
        }
        float l[4][8];
#pragma unroll
        for (int i=0;i<4;i++)
#pragma unroll
            for (int j=0;j<8;j++) l[i][j]=0.f;
#pragma unroll 5
        for (int d=0; d<HDIM; d++){
            float kv[8];
#pragma unroll
            for (int j=0;j<8;j++) kv[j] = kT[d*KSTR + lane + 32*j];
#pragma unroll
            for (int i=0;i<4;i++){
                float qv = (d<32)? __shfl_sync(0xffffffffu, qd[i], d)
                                 : __shfl_sync(0xffffffffu, qd2[i], d-32);
#pragma unroll
                for (int j=0;j<8;j++) l[i][j] += qv*kv[j];
            }
        }
#pragma unroll
        for (int i=0;i<4;i++){
            float mx = -1e30f;
#pragma unroll
            for (int j=0;j<8;j++){ l[i][j] *= rs; mx = fmaxf(mx, l[i][j]); }
#pragma unroll
            for (int o=16;o;o>>=1) mx = fmaxf(mx, __shfl_xor_sync(0xffffffffu, mx, o));
            float sum = 0.f;
#pragma unroll
            for (int j=0;j<8;j++){ l[i][j] = expf(l[i][j]-mx); sum += l[i][j]; }
#pragma unroll
            for (int o=16;o;o>>=1) sum += __shfl_xor_sync(0xffffffffu, sum, o);
            float inv = 1.0f/sum;
#pragma unroll
            for (int j=0;j<8;j++) ps[(wid*4+i)*256 + lane + 32*j] = l[i][j]*inv;
        }
        __syncwarp();
        float a0[4]={0,0,0,0}, a1[4]={0,0,0,0};
        int d2ok = (lane<3);
#pragma unroll 2
        for (int m=0;m<256;m+=4){
            float4 vv  = *(const float4*)&vT[lane*KSTR+m];
            float4 vv2 = d2ok ? *(const float4*)&vT[(lane+32)*KSTR+m]
                              : make_float4(0.f,0.f,0.f,0.f);
#pragma unroll
            for (int i=0;i<4;i++){
                float4 pm = *(const float4*)&ps[(wid*4+i)*256+m];
                a0[i] += pm.x*vv.x + pm.y*vv.y + pm.z*vv.z + pm.w*vv.w;
                a1[i] += pm.x*vv2.x + pm.y*vv2.y + pm.z*vv2.z + pm.w*vv2.w;
            }
        }
#pragma unroll
        for (int i=0;i<4;i++){
            float* orow = g_aca + ((size_t)b*NTOK + tq[i])*CDIM + head*HDIM;
            orow[lane] = a0[i];
            if (lane<3) orow[lane+32] = a1[i];
        }
        __syncwarp();
    }
}

__global__ __launch_bounds__(256,2) void winattn_kernel(const float* __restrict__ mask)
{
    extern __shared__ float sm[];
    float* kT = sm;
    float* vT = sm + 35*KSTR;
    float* ps = sm + 2*35*KSTR;
    int*  tok = (int*)(sm + 2*35*KSTR + 8*4*256);
    int head = blockIdx.x, win = blockIdx.y, b = blockIdx.z;
    int wh = win>>3, ww = win&7;
    int tid = threadIdx.x, wid = tid>>5, lane = tid&31;
    {
        int i = tid;
        int y  = ((wh<<4) + (i>>4) + 8) & 127;
        int xq = ((ww<<4) + (i&15) + 8) & 127;
        tok[i] = y*128 + xq;
    }
    __syncthreads();
    const float* qb = g_qkv + (size_t)b*NTOK*C3;
    for (int i=wid; i<256; i+=8){
        const float* p = qb + (size_t)tok[i]*C3 + head*HDIM;
        kT[lane*KSTR+i] = p[CDIM + lane];
        vT[lane*KSTR+i] = p[2*CDIM + lane];
        if (lane<3){
            kT[(lane+32)*KSTR+i] = p[CDIM + lane+32];
            vT[(lane+32)*KSTR+i] = p[2*CDIM + lane+32];
        }
    }
    __syncthreads();
    const float rs = 0.16903085094570331f;
    for (int it=0; it<8; it++){
        int qi0 = wid*32 + it*4;
        int tq[4]; float qd[4], qd2[4];
#pragma unroll
        for (int i=0;i<4;i++){
            tq[i] = tok[qi0+i];
            const float* qp = qb + (size_t)tq[i]*C3 + head*HDIM;
            qd[i]  = qp[lane];
            qd2[i] = (lane<3)? qp[lane+32] : 0.f;
        }
        float l[4][8];
#pragma unroll
        for (int i=0;i<4;i++)
#pragma unroll
            for (int j=0;j<8;j++) l[i][j]=0.f;
#pragma unroll 5
        for (int d=0; d<HDIM; d++){
            float kv[8];
#pragma unroll
            for (int j=0;j<8;j++) kv[j] = kT[d*KSTR + lane + 32*j];
#pragma unroll
            for (int i=0;i<4;i++){
                float qv = (d<32)? __shfl_sync(0xffffffffu, qd[i], d)
                                 : __shfl_sync(0xffffffffu, qd2[i], d-32);
#pragma unroll
                for (int j=0;j<8;j++) l[i][j] += qv*kv[j];
            }
        }
#pragma unroll
        for (int i=0;i<4;i++){
            const float* brow = g_biasf + head*65536 + (qi0+i)*256;
            const float* mrow = mask + (size_t)win*65536 + (qi0+i)*256;
            float mx = -1e30f;
#pragma unroll
            for (int j=0;j<8;j++){
                l[i][j] = l[i][j]*rs + brow[lane+32*j] + mrow[lane+32*j];
                mx = fmaxf(mx, l[i][j]);
            }
#pragma unroll
            for (int o=16;o;o>>=1) mx = fmaxf(mx, __shfl_xor_sync(0xffffffffu, mx, o));
            float sum = 0.f;
#pragma unroll
            for (int j=0;j<8;j++){ l[i][j] = expf(l[i][j]-mx); sum += l[i][j]; }
#pragma unroll
            for (int o=16;o;o>>=1) sum += __shfl_xor_sync(0xffffffffu, sum, o);
            float inv = 1.0f/sum;
#pragma unroll
            for (int j=0;j<8;j++) ps[(wid*4+i)*256 + lane + 32*j] = l[i][j]*inv;
        }
        __syncwarp();
        float a0[4]={0,0,0,0}, a1[4]={0,0,0,0};
        int d2ok = (lane<3);
#pragma unroll 2
        for (int m=0;m<256;m+=4){
            float4 vv  = *(const float4*)&vT[lane*KSTR+m];
            float4 vv2 = d2ok ? *(const float4*)&vT[(lane+32)*KSTR+m]
                              : make_float4(0.f,0.f,0.f,0.f);
#pragma unroll
            for (int i=0;i<4;i++){
                float4 pm = *(const float4*)&ps[(wid*4+i)*256+m];
                a0[i] += pm.x*vv.x + pm.y*vv.y + pm.z*vv.z + pm.w*vv.w;
                a1[i] += pm.x*vv2.x + pm.y*vv2.y + pm.z*vv2.z + pm.w*vv2.w;
            }
        }
#pragma unroll
        for (int i=0;i<4;i++){
            float* orow = g_win + ((size_t)b*NTOK + tq[i])*CDIM + head*HDIM;
            orow[lane] = a0[i];
            if (lane<3) orow[lane+32] = a1[i];
        }
        __syncwarp();
    }
}

// ---------- gather td features into hcat[:,420:516] ----------
__global__ void tdgather_kernel()
{
    int i = blockIdx.x*256 + threadIdx.x;
    int row = i/96, j = i - row*96;
    int b = row >> 14;
    int tk = g_tkid[row];
    g_hcat[(size_t)row*HF2C + MLPH + j] = g_ftd[((b<<7)+tk)*DTD + j];
}

// ---------- depthwise 5x5 conv + gelu + residual ----------
__global__ __launch_bounds__(256) void conv_kernel(const float* __restrict__ dw_w,
                                                   const float* __restrict__ dw_b)
{
    __shared__ float s[144*32];
    __shared__ float wsm[32*25];
    int c0 = blockIdx.x*32;
    int tile = blockIdx.y;
    int ty0=(tile>>4)*8, tx0=(tile&15)*8;
    int b = blockIdx.z;
    int cx = threadIdx.x, py = threadIdx.y;
    int tid = py*32+cx;
    for (int f=tid; f<144*32; f+=256){
        int p=f>>5, ch=f&31;
        int gy=ty0-2+p/12, gx=tx0-2+p%12;
        int c=c0+ch;
        float v=0.f;
        if (gy>=0&&gy<128&&gx>=0&&gx<128&&c<HF2C)
            v = g_hcat[((size_t)(b*NTOK+gy*128+gx))*HF2C + c];
        s[f]=v;
    }
    for (int f=tid; f<32*25; f+=256){
        int ch=f/25, k=f-ch*25; int c=c0+ch;
        wsm[f] = (c<HF2C)? dw_w[c*25+k] : 0.f;
    }
    __syncthreads();
    int c = c0+cx;
    if (c>=HF2C) return;
    float bsv = dw_b[c];
    float wr[25];
#pragma unroll
    for (int k=0;k<25;k++) wr[k]=wsm[cx*25+k];
    for (int px=0;px<8;px++){
        float acc=0.f;
#pragma unroll
        for (int ky=0;ky<5;ky++)
#pragma unroll
            for (int kx=0;kx<5;kx++)
                acc += wr[ky*5+kx]*s[((py+ky)*12+px+kx)*32+cx];
        float center = s[((py+2)*12+px+2)*32+cx];
        float o = center + gelu_exact(acc+bsv);
        g_hcat2[((size_t)(b*NTOK+(ty0+py)*128+(tx0+px)))*HF2C + c] = o;
    }
}

#define ATD_SMEM ((MTOK*CDIM + DRED*MTOK + 8*4*MTOK)*4)

static int find_nth(const int* s, int n, int sz, int nth){
    int c=0;
    for (int i=0;i<n;i++){ if (s[i]==sz){ if (c==nth) return i; c++; } }
    return 0;
}

extern "C" void kernel_launch(void* const* d_in, const int* in_sizes, int n_in,
                              void* d_out, int out_size)
{
    const float *x,*td,*attn_mask,*g1,*b1,*g2,*b2,*wqkv_w,*wqkv_b,*wq_w,*wq_b;
    const float *wk_w,*wk_b,*wv_w,*wv_b,*atd_scale,*aca_w,*aca_b,*rpb,*winp_w,*winp_b;
    const float *fctd_w,*fctd_b,*fc1_w,*fc1_b,*dw_w,*dw_b,*fc2_w,*fc2_b;
    const int *rpi;

    if (in_sizes[0] == 13762560){
        bool sig = (in_sizes[2] > 1000000);
        x         = (const float*)d_in[0];
        td        = (const float*)d_in[1];
        attn_mask = (const float*)(sig ? d_in[2] : d_in[29]);
        int k = sig ? 3 : 2;
        g1 = (const float*)d_in[k+0];   b1 = (const float*)d_in[k+1];
        g2 = (const float*)d_in[k+2];   b2 = (const float*)d_in[k+3];
        wqkv_w = (const float*)d_in[k+4]; wqkv_b = (const float*)d_in[k+5];
        wq_w = (const float*)d_in[k+6];  wq_b = (const float*)d_in[k+7];
        wk_w = (const float*)d_in[k+8];  wk_b = (const float*)d_in[k+9];
        wv_w = (const float*)d_in[k+10]; wv_b = (const float*)d_in[k+11];
        atd_scale = (const float*)d_in[k+12];
        aca_w = (const float*)d_in[k+13]; aca_b = (const float*)d_in[k+14];
        rpb = (const float*)d_in[k+15];
        winp_w = (const float*)d_in[k+16]; winp_b = (const float*)d_in[k+17];
        fctd_w = (const float*)d_in[k+18]; fctd_b = (const float*)d_in[k+19];
        fc1_w = (const float*)d_in[k+20]; fc1_b = (const float*)d_in[k+21];
        dw_w = (const float*)d_in[k+22];  dw_b = (const float*)d_in[k+23];
        fc2_w = (const float*)d_in[k+24]; fc2_b = (const float*)d_in[k+25];
        rpi = (const int*)d_in[k+26];
    } else {
        x         = (const float*)d_in[find_nth(in_sizes,n_in,13762560,0)];
        td        = (const float*)d_in[find_nth(in_sizes,n_in,107520,0)];
        attn_mask = (const float*)d_in[find_nth(in_sizes,n_in,4194304,0)];
        wqkv_w    = (const float*)d_in[find_nth(in_sizes,n_in,132300,0)];
        wqkv_b    = (const float*)d_in[find_nth(in_sizes,n_in,630,0)];
        fc2_w     = (const float*)d_in[find_nth(in_sizes,n_in,108360,0)];
        fc1_w     = (const float*)d_in[find_nth(in_sizes,n_in,88200,0)];
        fc1_b     = (const float*)d_in[find_nth(in_sizes,n_in,420,0)];
        fctd_w    = (const float*)d_in[find_nth(in_sizes,n_in,20160,0)];
        fctd_b    = (const float*)d_in[find_nth(in_sizes,n_in,96,0)];
        dw_w      = (const float*)d_in[find_nth(in_sizes,n_in,12900,0)];
        dw_b      = (const float*)d_in[find_nth(in_sizes,n_in,516,0)];
        rpb       = (const float*)d_in[find_nth(in_sizes,n_in,5766,0)];
        rpi       = (const int*)  d_in[find_nth(in_sizes,n_in,65536,0)];
        aca_w  = (const float*)d_in[find_nth(in_sizes,n_in,44100,0)];
        winp_w = (const float*)d_in[find_nth(in_sizes,n_in,44100,1)];
        wv_w   = (const float*)d_in[find_nth(in_sizes,n_in,44100,2)];
        wk_w = (const float*)d_in[find_nth(in_sizes,n_in,4200,0)];
        wq_w = (const float*)d_in[find_nth(in_sizes,n_in,4200,1)];
        wk_b = (const float*)d_in[find_nth(in_sizes,n_in,20,0)];
        wq_b = (const float*)d_in[find_nth(in_sizes,n_in,20,1)];
        aca_b  = (const float*)d_in[find_nth(in_sizes,n_in,210,0)];
        b1     = (const float*)d_in[find_nth(in_sizes,n_in,210,1)];
        b2     = (const float*)d_in[find_nth(in_sizes,n_in,210,2)];
        fc2_b  = (const float*)d_in[find_nth(in_sizes,n_in,210,3)];
        g1     = (const float*)d_in[find_nth(in_sizes,n_in,210,4)];
        g2     = (const float*)d_in[find_nth(in_sizes,n_in,210,5)];
        winp_b = (const float*)d_in[find_nth(in_sizes,n_in,210,6)];
        wv_b   = (const float*)d_in[find_nth(in_sizes,n_in,210,7)];
        atd_scale = (const float*)d_in[find_nth(in_sizes,n_in,1,0)];
    }

    float *p_xn, *p_qkv, *p_x2, *p_xn2, *p_aca, *p_win, *p_hcat, *p_hcat2;
    cudaGetSymbolAddress((void**)&p_xn,    g_xn);
    cudaGetSymbolAddress((void**)&p_qkv,   g_qkv);
    cudaGetSymbolAddress((void**)&p_x2,    g_x2);
    cudaGetSymbolAddress((void**)&p_xn2,   g_xn2);
    cudaGetSymbolAddress((void**)&p_aca,   g_aca);
    cudaGetSymbolAddress((void**)&p_win,   g_win);
    cudaGetSymbolAddress((void**)&p_hcat,  g_hcat);
    cudaGetSymbolAddress((void**)&p_hcat2, g_hcat2);

    cudaFuncSetAttribute(atd_kernel,    cudaFuncAttributeMaxDynamicSharedMemorySize, ATD_SMEM);
    cudaFuncSetAttribute(acmsa_kernel,  cudaFuncAttributeMaxDynamicSharedMemorySize, ATT_SMEM);
    cudaFuncSetAttribute(winattn_kernel,cudaFuncAttributeMaxDynamicSharedMemorySize, ATT_SMEM);

    cudaStream_t s1;
    cudaStreamCreateWithFlags(&s1, cudaStreamNonBlocking);
    cudaEvent_t e0, eLN, eAux, eQKV, eW, eAtd, eTd;
    cudaEventCreateWithFlags(&e0,  cudaEventDisableTiming);
    cudaEventCreateWithFlags(&eLN, cudaEventDisableTiming);
    cudaEventCreateWithFlags(&eAux,cudaEventDisableTiming);
    cudaEventCreateWithFlags(&eQKV,cudaEventDisableTiming);
    cudaEventCreateWithFlags(&eW, cudaEventDisableTiming);
    cudaEventCreateWithFlags(&eAtd,cudaEventDisableTiming);
    cudaEventCreateWithFlags(&eTd, cudaEventDisableTiming);

    cudaEventRecord(e0, 0);
    cudaStreamWaitEvent(s1, e0, 0);

    biasprep_kernel<<<256,256,0,s1>>>(rpb, rpi);
    kv_kernel<<<BATCH*MTOK,256,0,s1>>>(td, wk_w,wk_b, wv_w,wv_b, fctd_w,fctd_b);

    ln_kernel<<<ROWS/8,256>>>(x, g1, b1, p_xn, ROWS);
    cudaEventRecord(eLN, 0);
    cudaStreamWaitEvent(s1, eLN, 0);
    sgemm_kernel<<<dim3(5,512),256>>>(p_xn,CDIM, wqkv_w,C3, wqkv_b, nullptr,0,
                                      p_qkv,C3, ROWS,C3,CDIM, 0);
    cudaEventRecord(eQKV, 0);

    qproj_kernel<<<ROWS/4,128,0,s1>>>(wq_w, wq_b);
    cudaEventRecord(eAux, s1);

    cudaStreamWaitEvent(s1, eQKV, 0);
    winattn_kernel<<<dim3(6,64,BATCH),256,ATT_SMEM,s1>>>(attn_mask);
    cudaEventRecord(eW, s1);

    cudaStreamWaitEvent(0, eAux, 0);
    atd_kernel<<<BATCH*256,256,ATD_SMEM>>>(x, atd_scale);
    cudaEventRecord(eAtd, 0);
    sort_kernel<<<BATCH,64>>>();
    acmsa_kernel<<<dim3(6,64,BATCH),256,ATT_SMEM>>>();

    // s1: td gather overlaps with dual projection / ln2 / fc1
    cudaStreamWaitEvent(s1, eAtd, 0);
    tdgather_kernel<<<ROWS*96/256,256,0,s1>>>();
    cudaEventRecord(eTd, s1);

    cudaStreamWaitEvent(0, eW, 0);
    sgemm_dual<<<dim3(2,512),256>>>(p_aca, p_win, aca_w, winp_w, aca_b, winp_b, p_x2);

    ln_kernel<<<ROWS/8,256>>>(p_x2, g2, b2, p_xn2, ROWS);
    sgemm_kernel<<<dim3(4,512),256>>>(p_xn2,CDIM, fc1_w,MLPH, fc1_b, nullptr,0,
                                      p_hcat,HF2C, ROWS,MLPH,CDIM, 1);
    cudaStreamWaitEvent(0, eTd, 0);
    conv_kernel<<<dim3(17,256,BATCH),dim3(32,8)>>>(dw_w, dw_b);
    sgemm_kernel<<<dim3(2,512),256>>>(p_hcat2,HF2C, fc2_w,CDIM, fc2_b, p_x2,CDIM,
                                      (float*)d_out,CDIM, ROWS,CDIM,HF2C, 0);
}

// round 13
// speedup vs baseline: 1.0228x; 1.0228x over previous
#include <cuda_runtime.h>
#include <math.h>
#include <stdint.h>

#define BATCH 4
#define NTOK 16384
#define CDIM 210
#define C3   630
#define HDIM 35
#define MTOK 128
#define DRED 20
#define DTD 96
#define MLPH 420
#define HF2C 516
#define ROWS (BATCH*NTOK)
#define LOGM 4.852030263919617f

__device__ float g_xn  [ROWS*CDIM];
__device__ float g_qkv [(size_t)ROWS*C3];
__device__ float g_x2  [ROWS*CDIM];
__device__ float g_xn2 [ROWS*CDIM];
__device__ float g_q   [ROWS*DRED];
__device__ float g_kn  [BATCH*MTOK*DRED];
__device__ float g_v   [BATCH*MTOK*CDIM];
__device__ float g_ftd [BATCH*MTOK*DTD];
__device__ int   g_tkid[ROWS];
__device__ int   g_sidx[ROWS];
__device__ float g_aca [ROWS*CDIM];
__device__ float g_win [ROWS*CDIM];
__device__ float g_biasf[6*65536];
__device__ float g_hcat [(size_t)ROWS*HF2C];
__device__ float g_hcat2[(size_t)ROWS*HF2C];

__device__ __forceinline__ float gelu_exact(float v){
    return 0.5f*v*(1.0f+erff(v*0.7071067811865476f));
}

// ---- packed f32x2 helpers (Blackwell family feature, PTX >= 8.6, sm_100+) ----
__device__ __forceinline__ unsigned long long pk2(float lo, float hi){
    unsigned long long r;
    asm("mov.b64 %0, {%1,%2};" : "=l"(r) : "f"(lo), "f"(hi));
    return r;
}
__device__ __forceinline__ void fma2(unsigned long long &d, unsigned long long a,
                                     unsigned long long b){
    asm("fma.rn.f32x2 %0, %1, %2, %0;" : "+l"(d) : "l"(a), "l"(b));
}
__device__ __forceinline__ float2 upk2(unsigned long long v){
    float2 f;
    asm("mov.b64 {%0,%1}, %2;" : "=f"(f.x), "=f"(f.y) : "l"(v));
    return f;
}

// ---------- LayerNorm: warp per row ----------
__global__ void ln_kernel(const float* __restrict__ in, const float* __restrict__ gam,
                          const float* __restrict__ bet, float* __restrict__ out, int rows)
{
    int warp = (blockIdx.x*blockDim.x + threadIdx.x) >> 5;
    int lane = threadIdx.x & 31;
    if (warp >= rows) return;
    const float* r = in + (size_t)warp*CDIM;
    float v[7]; float s = 0.f;
#pragma unroll
    for (int j=0;j<7;j++){ int k = lane + 32*j; v[j] = (k<CDIM)? r[k] : 0.f; s += v[j]; }
#pragma unroll
    for (int o=16;o;o>>=1) s += __shfl_xor_sync(0xffffffffu, s, o);
    float mu = s * (1.0f/CDIM);
    float vs = 0.f;
#pragma unroll
    for (int j=0;j<7;j++){ int k = lane + 32*j; if (k<CDIM){ float d = v[j]-mu; vs += d*d; } }
#pragma unroll
    for (int o=16;o;o>>=1) vs += __shfl_xor_sync(0xffffffffu, vs, o);
    float rstd = rsqrtf(vs*(1.0f/CDIM) + 1e-5f);
    float* o2 = out + (size_t)warp*CDIM;
#pragma unroll
    for (int j=0;j<7;j++){ int k = lane + 32*j; if (k<CDIM) o2[k] = (v[j]-mu)*rstd*gam[k] + bet[k]; }
}

// ---------- SGEMM: double-buffered 128x128x8, 8x8/thread, FFMA2 core ----------
__global__ __launch_bounds__(256,2) void sgemm_kernel(
        const float* __restrict__ A, int lda,
        const float* __restrict__ W, int ldw,
        const float* __restrict__ bias,
        const float* __restrict__ addp, int ldadd,
        float* __restrict__ C, int ldc,
        int Mr, int Nc, int K, int act)
{
    __shared__ float As[2][8][128];
    __shared__ float Bs[2][8][128];
    int tid = threadIdx.x;
    int tx = tid & 15, ty = tid >> 4;
    int row0 = blockIdx.y * 128, col0 = blockIdx.x * 128;
    unsigned long long acc2[8][4];
#pragma unroll
    for (int i=0;i<8;i++)
#pragma unroll
        for (int j=0;j<4;j++) acc2[i][j]=0ull;
    int nk = (K+7)/8;
    float ra[4], rb[4];
    {
#pragma unroll
        for (int i=0;i<4;i++){
            int f = tid + i*256;
            int r = f>>3, kk = f&7;
            int gr = row0+r;
            ra[i] = (gr<Mr && kk<K)? A[(size_t)gr*lda + kk] : 0.f;
            int kb = f>>7, cb = f&127;
            int gc = col0+cb;
            rb[i] = (kb<K && gc<Nc)? W[(size_t)kb*ldw + gc] : 0.f;
        }
#pragma unroll
        for (int i=0;i<4;i++){
            int f = tid + i*256;
            As[0][f&7][f>>3] = ra[i];
            Bs[0][f>>7][f&127] = rb[i];
        }
    }
    __syncthreads();
    for (int kt=0; kt<nk; kt++){
        int cur = kt&1;
        if (kt+1 < nk){
            int k0 = (kt+1)*8;
#pragma unroll
            for (int i=0;i<4;i++){
                int f = tid + i*256;
                int r = f>>3, kk = f&7;
                int gr = row0+r, gk = k0+kk;
                ra[i] = (gr<Mr && gk<K)? A[(size_t)gr*lda + gk] : 0.f;
                int kb = f>>7, cb = f&127;
                int gc = col0+cb, gkb = k0+kb;
                rb[i] = (gkb<K && gc<Nc)? W[(size_t)gkb*ldw + gc] : 0.f;
            }
        }
#pragma unroll
        for (int kk=0;kk<8;kk++){
            float4 a0 = *(const float4*)&As[cur][kk][ty*8];
            float4 a1 = *(const float4*)&As[cur][kk][ty*8+4];
            float4 b0 = *(const float4*)&Bs[cur][kk][tx*8];
            float4 b1 = *(const float4*)&Bs[cur][kk][tx*8+4];
            unsigned long long bp[4];
            bp[0] = pk2(b0.x,b0.y); bp[1] = pk2(b0.z,b0.w);
            bp[2] = pk2(b1.x,b1.y); bp[3] = pk2(b1.z,b1.w);
            float av[8] = {a0.x,a0.y,a0.z,a0.w,a1.x,a1.y,a1.z,a1.w};
#pragma unroll
            for (int i=0;i<8;i++){
                unsigned long long ap = pk2(av[i],av[i]);
#pragma unroll
                for (int j=0;j<4;j++) fma2(acc2[i][j], ap, bp[j]);
            }
        }
        if (kt+1 < nk){
            int nxt = cur^1;
#pragma unroll
            for (int i=0;i<4;i++){
                int f = tid + i*256;
                As[nxt][f&7][f>>3] = ra[i];
                Bs[nxt][f>>7][f&127] = rb[i];
            }
            __syncthreads();
        }
    }
#pragma unroll
    for (int i=0;i<8;i++){
        int r = row0 + ty*8 + i;
        if (r >= Mr) continue;
#pragma unroll
        for (int jp=0;jp<4;jp++){
            float2 p = upk2(acc2[i][jp]);
            float vals[2] = {p.x, p.y};
#pragma unroll
            for (int h=0;h<2;h++){
                int c = col0 + tx*8 + jp*2 + h;
                if (c >= Nc) continue;
                float v = vals[h] + bias[c];
                if (act==1) v = gelu_exact(v);
                if (addp) v += addp[(size_t)r*ldadd + c];
                C[(size_t)r*ldc + c] = v;
            }
        }
    }
}

// ---------- fused dual-projection GEMM: x2 += aca@W1 + win@W2 + b1 + b2 ----------
__global__ __launch_bounds__(256,2) void sgemm_dual(
        const float* __restrict__ A1, const float* __restrict__ A2,
        const float* __restrict__ W1, const float* __restrict__ W2,
        const float* __restrict__ b1v, const float* __restrict__ b2v,
        float* __restrict__ C)
{
    __shared__ float As[2][8][128];
    __shared__ float Bs[2][8][128];
    int tid = threadIdx.x;
    int tx = tid & 15, ty = tid >> 4;
    int row0 = blockIdx.y * 128, col0 = blockIdx.x * 128;
    unsigned long long acc2[8][4];
#pragma unroll
    for (int i=0;i<8;i++)
#pragma unroll
        for (int j=0;j<4;j++) acc2[i][j]=0ull;
    const int K = 420, Nc = 210;
    int nk = (K+7)/8;
    float ra[4], rb[4];
    {
#pragma unroll
        for (int i=0;i<4;i++){
            int f = tid + i*256;
            int r = row0 + (f>>3), kk = f&7;
            ra[i] = A1[(size_t)r*210 + kk];
            int kb = f>>7, cb = f&127;
            int gc = col0+cb;
            rb[i] = (gc<Nc)? W1[kb*210 + gc] : 0.f;
        }
#pragma unroll
        for (int i=0;i<4;i++){
            int f = tid + i*256;
            As[0][f&7][f>>3] = ra[i];
            Bs[0][f>>7][f&127] = rb[i];
        }
    }
    __syncthreads();
    for (int kt=0; kt<nk; kt++){
        int cur = kt&1;
        if (kt+1 < nk){
            int k0 = (kt+1)*8;
#pragma unroll
            for (int i=0;i<4;i++){
                int f = tid + i*256;
                int r = row0 + (f>>3), gk = k0 + (f&7);
                float a = 0.f;
                if (gk < 210)       a = A1[(size_t)r*210 + gk];
                else if (gk < 420)  a = A2[(size_t)r*210 + gk-210];
                ra[i] = a;
                int gkb = k0 + (f>>7), cb = f&127;
                int gc = col0+cb;
                float b = 0.f;
                if (gc < Nc){
                    if (gkb < 210)      b = W1[gkb*210 + gc];
                    else if (gkb < 420) b = W2[(gkb-210)*210 + gc];
                }
                rb[i] = b;
            }
        }
#pragma unroll
        for (int kk=0;kk<8;kk++){
            float4 a0 = *(const float4*)&As[cur][kk][ty*8];
            float4 a1 = *(const float4*)&As[cur][kk][ty*8+4];
            float4 b0 = *(const float4*)&Bs[cur][kk][tx*8];
            float4 b1 = *(const float4*)&Bs[cur][kk][tx*8+4];
            unsigned long long bp[4];
            bp[0] = pk2(b0.x,b0.y); bp[1] = pk2(b0.z,b0.w);
            bp[2] = pk2(b1.x,b1.y); bp[3] = pk2(b1.z,b1.w);
            float av[8] = {a0.x,a0.y,a0.z,a0.w,a1.x,a1.y,a1.z,a1.w};
#pragma unroll
            for (int i=0;i<8;i++){
                unsigned long long ap = pk2(av[i],av[i]);
#pragma unroll
                for (int j=0;j<4;j++) fma2(acc2[i][j], ap, bp[j]);
            }
        }
        if (kt+1 < nk){
            int nxt = cur^1;
#pragma unroll
            for (int i=0;i<4;i++){
                int f = tid + i*256;
                As[nxt][f&7][f>>3] = ra[i];
                Bs[nxt][f>>7][f&127] = rb[i];
            }
            __syncthreads();
        }
    }
#pragma unroll
    for (int i=0;i<8;i++){
        int r = row0 + ty*8 + i;
#pragma unroll
        for (int jp=0;jp<4;jp++){
            float2 p = upk2(acc2[i][jp]);
            float vals[2] = {p.x, p.y};
#pragma unroll
            for (int h=0;h<2;h++){
                int c = col0 + tx*8 + jp*2 + h;
                if (c >= Nc) continue;
                size_t idx = (size_t)r*210 + c;
                C[idx] = C[idx] + vals[h] + b1v[c] + b2v[c];
            }
        }
    }
}

// ---------- q projection + l2norm: warp per row ----------
__global__ void qproj_kernel(const float* __restrict__ wq, const float* __restrict__ bq)
{
    __shared__ float s[4][CDIM];
    int w = threadIdx.x>>5, lane = threadIdx.x&31;
    int row = blockIdx.x*4 + w;
    const float* r = g_xn + (size_t)row*CDIM;
    for (int k=lane;k<CDIM;k+=32) s[w][k] = r[k];
    __syncwarp();
    float acc = 0.f;
    if (lane < DRED){
        acc = bq[lane];
        for (int k=0;k<CDIM;k++) acc += s[w][k]*wq[k*DRED+lane];
    }
    float sq = (lane<DRED)? acc*acc : 0.f;
#pragma unroll
    for (int o=16;o;o>>=1) sq += __shfl_xor_sync(0xffffffffu, sq, o);
    float den = fmaxf(sqrtf(sq), 1e-12f);
    if (lane < DRED) g_q[(size_t)row*DRED + lane] = acc/den;
}

// ---------- td projections ----------
__global__ void kv_kernel(const float* __restrict__ td,
                          const float* __restrict__ wk_w, const float* __restrict__ wk_b,
                          const float* __restrict__ wv_w, const float* __restrict__ wv_b,
                          const float* __restrict__ ftd_w, const float* __restrict__ ftd_b)
{
    __shared__ float tr[CDIM];
    __shared__ float ks_s[DRED];
    __shared__ float nrm_s;
    int rm = blockIdx.x;
    int b = rm >> 7, m = rm & 127;
    int t = threadIdx.x;
    const float* trow = td + (size_t)rm*CDIM;
    if (t < CDIM) tr[t] = trow[t];
    __syncthreads();
    if (t < CDIM){
        float a = wv_b[t];
        for (int k=0;k<CDIM;k++) a += tr[k]*wv_w[k*CDIM+t];
        g_v[(size_t)rm*CDIM + t] = a;
    }
    if (t < DTD){
        float a = ftd_b[t];
        for (int k=0;k<CDIM;k++) a += tr[k]*ftd_w[k*DTD+t];
        g_ftd[(size_t)rm*DTD + t] = a;
    }
    if (t < DRED){
        float a = wk_b[t];
        for (int k=0;k<CDIM;k++) a += tr[k]*wk_w[k*DRED+t];
        ks_s[t] = a;
    }
    __syncthreads();
    if (t==0){
        float s=0.f;
        for (int j=0;j<DRED;j++) s += ks_s[j]*ks_s[j];
        nrm_s = fmaxf(sqrtf(s), 1e-12f);
    }
    __syncthreads();
    if (t < DRED) g_kn[b*(MTOK*DRED) + t*MTOK + m] = ks_s[t]/nrm_s;
}

// ---------- fused ATD cross-attn (4 tokens/warp-iter) ----------
__global__ void atd_kernel(const float* __restrict__ x, const float* __restrict__ atd_scale)
{
    extern __shared__ float sm2[];
    float* vs  = sm2;
    float* knT = vs + MTOK*CDIM;
    float* pbuf= knT + DRED*MTOK;
    int tid = threadIdx.x, wid = tid>>5, lane = tid&31;
    int b  = blockIdx.x >> 8;
    int n0 = (blockIdx.x & 255) * 64;
    for (int f=tid; f<MTOK*CDIM; f+=256) vs[f]  = g_v [b*(MTOK*CDIM)+f];
    for (int f=tid; f<DRED*MTOK; f+=256) knT[f] = g_kn[b*(MTOK*DRED)+f];
    float sc = atd_scale[0];
    sc = 1.0f + fminf(fmaxf(sc,0.0f),3.0f)*LOGM;
    __syncthreads();
    for (int g=0; g<2; g++){
        int n = n0 + wid*8 + g*4;
        size_t rbase = (size_t)b*NTOK + n;
        float ql[4];
#pragma unroll
        for (int i=0;i<4;i++)
            ql[i] = (lane<DRED)? g_q[(rbase+i)*DRED + lane] : 0.f;
        float lg[4][4];
#pragma unroll
        for (int i=0;i<4;i++)
#pragma unroll
            for (int mm=0;mm<4;mm++) lg[i][mm]=0.f;
        for (int j=0;j<DRED;j++){
            float kv[4];
#pragma unroll
            for (int mm=0;mm<4;mm++) kv[mm] = knT[j*MTOK + lane + 32*mm];
#pragma unroll
            for (int i=0;i<4;i++){
                float qv = __shfl_sync(0xffffffffu, ql[i], j);
#pragma unroll
                for (int mm=0;mm<4;mm++) lg[i][mm] += qv*kv[mm];
            }
        }
#pragma unroll
        for (int i=0;i<4;i++){
#pragma unroll
            for (int mm=0;mm<4;mm++) lg[i][mm] *= sc;
            float bv = lg[i][0]; int bi = lane;
#pragma unroll
            for (int mm=1;mm<4;mm++){
                int m = lane+32*mm;
                if (lg[i][mm] > bv){ bv = lg[i][mm]; bi = m; }
            }
#pragma unroll
            for (int o=16;o;o>>=1){
                float ov = __shfl_xor_sync(0xffffffffu, bv, o);
                int   oi = __shfl_xor_sync(0xffffffffu, bi, o);
                if (ov > bv || (ov==bv && oi<bi)){ bv = ov; bi = oi; }
            }
            float sum = 0.f;
#pragma unroll
            for (int mm=0;mm<4;mm++){ lg[i][mm] = expf(lg[i][mm]-bv); sum += lg[i][mm]; }
#pragma unroll
            for (int o=16;o;o>>=1) sum += __shfl_xor_sync(0xffffffffu, sum, o);
            float inv = 1.0f/sum;
#pragma unroll
            for (int mm=0;mm<4;mm++) pbuf[(wid*4+i)*MTOK + lane + 32*mm] = lg[i][mm]*inv;
            if (lane==0) g_tkid[rbase+i] = bi;
        }
        __syncwarp();
        float a[4][7];
#pragma unroll
        for (int i=0;i<4;i++)
#pragma unroll
            for (int k=0;k<7;k++) a[i][k]=0.f;
#pragma unroll 2
        for (int m=0;m<MTOK;m++){
            float vv[7];
            const float* vrow = vs + m*CDIM;
#pragma unroll
            for (int k=0;k<6;k++) vv[k] = vrow[lane+32*k];
            vv[6] = (lane<18)? vrow[lane+192] : 0.f;
#pragma unroll
            for (int i=0;i<4;i++){
                float pm = pbuf[(wid*4+i)*MTOK + m];
#pragma unroll
                for (int k=0;k<7;k++) a[i][k] += pm*vv[k];
            }
        }
#pragma unroll
        for (int i=0;i<4;i++){
            const float* xr = x + (rbase+i)*CDIM;
            float* orow = g_x2 + (rbase+i)*CDIM;
#pragma unroll
            for (int k=0;k<6;k++) orow[lane+32*k] = xr[lane+32*k] + a[i][k];
            if (lane<18) orow[lane+192] = xr[lane+192] + a[i][6];
        }
        __syncwarp();
    }
}

// ---------- stable counting sort per batch ----------
__global__ void sort_kernel()
{
    __shared__ int cnt[64*128];
    __shared__ int binbase[128];
    int b = blockIdx.x, t = threadIdx.x;
    const int* key = g_tkid + b*NTOK;
    int* out = g_sidx + b*NTOK;
    for (int i=t;i<64*128;i+=64) cnt[i]=0;
    __syncthreads();
    for (int i=0;i<256;i++){ int k = key[t*256+i]; cnt[t*128+k]++; }
    __syncthreads();
    for (int bb=t; bb<128; bb+=64){
        int tot=0;
        for (int th=0; th<64; th++){ int v = cnt[th*128+bb]; cnt[th*128+bb]=tot; tot+=v; }
        binbase[bb]=tot;
    }
    __syncthreads();
    if (t==0){ int s=0; for (int bn=0;bn<128;bn++){ int v=binbase[bn]; binbase[bn]=s; s+=v; } }
    __syncthreads();
    for (int i=0;i<256;i++){
        int tok = t*256+i;
        int k = key[tok];
        int pos = binbase[k] + cnt[t*128+k]++;
        out[pos] = tok;
    }
}

// ---------- window bias precompute ----------
__global__ void biasprep_kernel(const float* __restrict__ rpb, const int* __restrict__ rpi)
{
    int i = blockIdx.x*256 + threadIdx.x;
    int r = rpi[i];
#pragma unroll
    for (int h=0;h<6;h++) g_biasf[h*65536 + i] = rpb[r*6 + h];
}

// ---------- attention core (stride 260, float4 PV) ----------
#define KSTR 260
#define ATT_SMEM ((2*35*KSTR + 8*4*256 + 256)*4)

__global__ __launch_bounds__(256,2) void acmsa_kernel()
{
    extern __shared__ float sm[];
    float* kT = sm;
    float* vT = sm + 35*KSTR;
    float* ps = sm + 2*35*KSTR;
    int*  tok = (int*)(sm + 2*35*KSTR + 8*4*256);
    int head = blockIdx.x, grp = blockIdx.y, b = blockIdx.z;
    int tid = threadIdx.x, wid = tid>>5, lane = tid&31;
    tok[tid] = g_sidx[b*NTOK + grp*256 + tid];
    __syncthreads();
    const float* qb = g_qkv + (size_t)b*NTOK*C3;
    for (int i=wid; i<256; i+=8){
        const float* p = qb + (size_t)tok[i]*C3 + head*HDIM;
        kT[lane*KSTR+i] = p[CDIM + lane];
        vT[lane*KSTR+i] = p[2*CDIM + lane];
        if (lane<3){
            kT[(lane+32)*KSTR+i] = p[CDIM + lane+32];
            vT[(lane+32)*KSTR+i] = p[2*CDIM + lane+32];
        }
    }
    __syncthreads();
    const float rs = 0.16903085094570331f;
    for (int it=0; it<8; it++){
        int qi0 = wid*32 + it*4;
        int tq[4]; float qd[4], qd2[4];
#pragma unroll
        for (int i=0;i<4;i++){
            tq[i] = tok[qi0+i];
            const float* qp = qb + (size_t)tq[i]*C3 + head*HDIM;
            qd[i]  = qp[lane];
            qd2[i] = (lane<3)? qp[lane+32] : 0.f;
        }
        float l[4][8];
#pragma unroll
        for (int i=0;i<4;i++)
#pragma unroll
            for (int j=0;j<8;j++) l[i][j]=0.f;
#pragma unroll 5
        for (int d=0; d<HDIM; d++){
            float kv[8];
#pragma unroll
            for (int j=0;j<8;j++) kv[j] = kT[d*KSTR + lane + 32*j];
#pragma unroll
            for (int i=0;i<4;i++){
                float qv = (d<32)? __shfl_sync(0xffffffffu, qd[i], d)
                                 : __shfl_sync(0xffffffffu, qd2[i], d-32);
#pragma unroll
                for (int j=0;j<8;j++) l[i][j] += qv*kv[j];
            }
        }
#pragma unroll
        for (int i=0;i<4;i++){
            float mx = -1e30f;
#pragma unroll
            for (int j=0;j<8;j++){ l[i][j] *= rs; mx = fmaxf(mx, l[i][j]); }
#pragma unroll
            for (int o=16;o;o>>=1) mx = fmaxf(mx, __shfl_xor_sync(0xffffffffu, mx, o));
            float sum = 0.f;
#pragma unroll
            for (int j=0;j<8;j++){ l[i][j] = expf(l[i][j]-mx); sum += l[i][j]; }
#pragma unroll
            for (int o=16;o;o>>=1) sum += __shfl_xor_sync(0xffffffffu, sum, o);
            float inv = 1.0f/sum;
#pragma unroll
            for (int j=0;j<8;j++) ps[(wid*4+i)*256 + lane + 32*j] = l[i][j]*inv;
        }
        __syncwarp();
        float a0[4]={0,0,0,0}, a1[4]={0,0,0,0};
        int d2ok = (lane<3);
#pragma unroll 2
        for (int m=0;m<256;m+=4){
            float4 vv  = *(const float4*)&vT[lane*KSTR+m];
            float4 vv2 = d2ok ? *(const float4*)&vT[(lane+32)*KSTR+m]
                              : make_float4(0.f,0.f,0.f,0.f);
#pragma unroll
            for (int i=0;i<4;i++){
                float4 pm = *(const float4*)&ps[(wid*4+i)*256+m];
                a0[i] += pm.x*vv.x + pm.y*vv.y + pm.z*vv.z + pm.w*vv.w;
                a1[i] += pm.x*vv2.x + pm.y*vv2.y + pm.z*vv2.z + pm.w*vv2.w;
            }
        }
#pragma unroll
        for (int i=0;i<4;i++){
            float* orow = g_aca + ((size_t)b*NTOK + tq[i])*CDIM + head*HDIM;
            orow[lane] = a0[i];
            if (lane<3) orow[lane+32] = a1[i];
        }
        __syncwarp();
    }
}

__global__ __launch_bounds__(256,2) void winattn_kernel(const float* __restrict__ mask)
{
    extern __shared__ float sm[];
    float* kT = sm;
    float* vT = sm + 35*KSTR;
    float* ps = sm + 2*35*KSTR;
    int*  tok = (int*)(sm + 2*35*KSTR + 8*4*256);
    int head = blockIdx.x, win = blockIdx.y, b = blockIdx.z;
    int wh = win>>3, ww = win&7;
    int tid = threadIdx.x, wid = tid>>5, lane = tid&31;
    {
        int i = tid;
        int y  = ((wh<<4) + (i>>4) + 8) & 127;
        int xq = ((ww<<4) + (i&15) + 8) & 127;
        tok[i] = y*128 + xq;
    }
    __syncthreads();
    const float* qb = g_qkv + (size_t)b*NTOK*C3;
    for (int i=wid; i<256; i+=8){
        const float* p = qb + (size_t)tok[i]*C3 + head*HDIM;
        kT[lane*KSTR+i] = p[CDIM + lane];
        vT[lane*KSTR+i] = p[2*CDIM + lane];
        if (lane<3){
            kT[(lane+32)*KSTR+i] = p[CDIM + lane+32];
            vT[(lane+32)*KSTR+i] = p[2*CDIM + lane+32];
        }
    }
    __syncthreads();
    const float rs = 0.16903085094570331f;
    for (int it=0; it<8; it++){
        int qi0 = wid*32 + it*4;
        int tq[4]; float qd[4], qd2[4];
#pragma unroll
        for (int i=0;i<4;i++){
            tq[i] = tok[qi0+i];
            const float* qp = qb + (size_t)tq[i]*C3 + head*HDIM;
            qd[i]  = qp[lane];
            qd2[i] = (lane<3)? qp[lane+32] : 0.f;
        }
        float l[4][8];
#pragma unroll
        for (int i=0;i<4;i++)
#pragma unroll
            for (int j=0;j<8;j++) l[i][j]=0.f;
#pragma unroll 5
        for (int d=0; d<HDIM; d++){
            float kv[8];
#pragma unroll
            for (int j=0;j<8;j++) kv[j] = kT[d*KSTR + lane + 32*j];
#pragma unroll
            for (int i=0;i<4;i++){
                float qv = (d<32)? __shfl_sync(0xffffffffu, qd[i], d)
                                 : __shfl_sync(0xffffffffu, qd2[i], d-32);
#pragma unroll
                for (int j=0;j<8;j++) l[i][j] += qv*kv[j];
            }
        }
#pragma unroll
        for (int i=0;i<4;i++){
            const float* brow = g_biasf + head*65536 + (qi0+i)*256;
            const float* mrow = mask + (size_t)win*65536 + (qi0+i)*256;
            float mx = -1e30f;
#pragma unroll
            for (int j=0;j<8;j++){
                l[i][j] = l[i][j]*rs + brow[lane+32*j] + mrow[lane+32*j];
                mx = fmaxf(mx, l[i][j]);
            }
#pragma unroll
            for (int o=16;o;o>>=1) mx = fmaxf(mx, __shfl_xor_sync(0xffffffffu, mx, o));
            float sum = 0.f;
#pragma unroll
            for (int j=0;j<8;j++){ l[i][j] = expf(l[i][j]-mx); sum += l[i][j]; }
#pragma unroll
            for (int o=16;o;o>>=1) sum += __shfl_xor_sync(0xffffffffu, sum, o);
            float inv = 1.0f/sum;
#pragma unroll
            for (int j=0;j<8;j++) ps[(wid*4+i)*256 + lane + 32*j] = l[i][j]*inv;
        }
        __syncwarp();
        float a0[4]={0,0,0,0}, a1[4]={0,0,0,0};
        int d2ok = (lane<3);
#pragma unroll 2
        for (int m=0;m<256;m+=4){
            float4 vv  = *(const float4*)&vT[lane*KSTR+m];
            float4 vv2 = d2ok ? *(const float4*)&vT[(lane+32)*KSTR+m]
                              : make_float4(0.f,0.f,0.f,0.f);
#pragma unroll
            for (int i=0;i<4;i++){
                float4 pm = *(const float4*)&ps[(wid*4+i)*256+m];
                a0[i] += pm.x*vv.x + pm.y*vv.y + pm.z*vv.z + pm.w*vv.w;
                a1[i] += pm.x*vv2.x + pm.y*vv2.y + pm.z*vv2.z + pm.w*vv2.w;
            }
        }
#pragma unroll
        for (int i=0;i<4;i++){
            float* orow = g_win + ((size_t)b*NTOK + tq[i])*CDIM + head*HDIM;
            orow[lane] = a0[i];
            if (lane<3) orow[lane+32] = a1[i];
        }
        __syncwarp();
    }
}

// ---------- gather td features into hcat[:,420:516] ----------
__global__ void tdgather_kernel()
{
    int i = blockIdx.x*256 + threadIdx.x;
    int row = i/96, j = i - row*96;
    int b = row >> 14;
    int tk = g_tkid[row];
    g_hcat[(size_t)row*HF2C + MLPH + j] = g_ftd[((b<<7)+tk)*DTD + j];
}

// ---------- depthwise 5x5 conv + gelu + residual ----------
__global__ __launch_bounds__(256) void conv_kernel(const float* __restrict__ dw_w,
                                                   const float* __restrict__ dw_b)
{
    __shared__ float s[144*32];
    __shared__ float wsm[32*25];
    int c0 = blockIdx.x*32;
    int tile = blockIdx.y;
    int ty0=(tile>>4)*8, tx0=(tile&15)*8;
    int b = blockIdx.z;
    int cx = threadIdx.x, py = threadIdx.y;
    int tid = py*32+cx;
    for (int f=tid; f<144*32; f+=256){
        int p=f>>5, ch=f&31;
        int gy=ty0-2+p/12, gx=tx0-2+p%12;
        int c=c0+ch;
        float v=0.f;
        if (gy>=0&&gy<128&&gx>=0&&gx<128&&c<HF2C)
            v = g_hcat[((size_t)(b*NTOK+gy*128+gx))*HF2C + c];
        s[f]=v;
    }
    for (int f=tid; f<32*25; f+=256){
        int ch=f/25, k=f-ch*25; int c=c0+ch;
        wsm[f] = (c<HF2C)? dw_w[c*25+k] : 0.f;
    }
    __syncthreads();
    int c = c0+cx;
    if (c>=HF2C) return;
    float bsv = dw_b[c];
    float wr[25];
#pragma unroll
    for (int k=0;k<25;k++) wr[k]=wsm[cx*25+k];
    for (int px=0;px<8;px++){
        float acc=0.f;
#pragma unroll
        for (int ky=0;ky<5;ky++)
#pragma unroll
            for (int kx=0;kx<5;kx++)
                acc += wr[ky*5+kx]*s[((py+ky)*12+px+kx)*32+cx];
        float center = s[((py+2)*12+px+2)*32+cx];
        float o = center + gelu_exact(acc+bsv);
        g_hcat2[((size_t)(b*NTOK+(ty0+py)*128+(tx0+px)))*HF2C + c] = o;
    }
}

#define ATD_SMEM ((MTOK*CDIM + DRED*MTOK + 8*4*MTOK)*4)

static int find_nth(const int* s, int n, int sz, int nth){
    int c=0;
    for (int i=0;i<n;i++){ if (s[i]==sz){ if (c==nth) return i; c++; } }
    return 0;
}

extern "C" void kernel_launch(void* const* d_in, const int* in_sizes, int n_in,
                              void* d_out, int out_size)
{
    const float *x,*td,*attn_mask,*g1,*b1,*g2,*b2,*wqkv_w,*wqkv_b,*wq_w,*wq_b;
    const float *wk_w,*wk_b,*wv_w,*wv_b,*atd_scale,*aca_w,*aca_b,*rpb,*winp_w,*winp_b;
    const float *fctd_w,*fctd_b,*fc1_w,*fc1_b,*dw_w,*dw_b,*fc2_w,*fc2_b;
    const int *rpi;

    if (in_sizes[0] == 13762560){
        bool sig = (in_sizes[2] > 1000000);
        x         = (const float*)d_in[0];
        td        = (const float*)d_in[1];
        attn_mask = (const float*)(sig ? d_in[2] : d_in[29]);
        int k = sig ? 3 : 2;
        g1 = (const float*)d_in[k+0];   b1 = (const float*)d_in[k+1];
        g2 = (const float*)d_in[k+2];   b2 = (const float*)d_in[k+3];
        wqkv_w = (const float*)d_in[k+4]; wqkv_b = (const float*)d_in[k+5];
        wq_w = (const float*)d_in[k+6];  wq_b = (const float*)d_in[k+7];
        wk_w = (const float*)d_in[k+8];  wk_b = (const float*)d_in[k+9];
        wv_w = (const float*)d_in[k+10]; wv_b = (const float*)d_in[k+11];
        atd_scale = (const float*)d_in[k+12];
        aca_w = (const float*)d_in[k+13]; aca_b = (const float*)d_in[k+14];
        rpb = (const float*)d_in[k+15];
        winp_w = (const float*)d_in[k+16]; winp_b = (const float*)d_in[k+17];
        fctd_w = (const float*)d_in[k+18]; fctd_b = (const float*)d_in[k+19];
        fc1_w = (const float*)d_in[k+20]; fc1_b = (const float*)d_in[k+21];
        dw_w = (const float*)d_in[k+22];  dw_b = (const float*)d_in[k+23];
        fc2_w = (const float*)d_in[k+24]; fc2_b = (const float*)d_in[k+25];
        rpi = (const int*)d_in[k+26];
    } else {
        x         = (const float*)d_in[find_nth(in_sizes,n_in,13762560,0)];
        td        = (const float*)d_in[find_nth(in_sizes,n_in,107520,0)];
        attn_mask = (const float*)d_in[find_nth(in_sizes,n_in,4194304,0)];
        wqkv_w    = (const float*)d_in[find_nth(in_sizes,n_in,132300,0)];
        wqkv_b    = (const float*)d_in[find_nth(in_sizes,n_in,630,0)];
        fc2_w     = (const float*)d_in[find_nth(in_sizes,n_in,108360,0)];
        fc1_w     = (const float*)d_in[find_nth(in_sizes,n_in,88200,0)];
        fc1_b     = (const float*)d_in[find_nth(in_sizes,n_in,420,0)];
        fctd_w    = (const float*)d_in[find_nth(in_sizes,n_in,20160,0)];
        fctd_b    = (const float*)d_in[find_nth(in_sizes,n_in,96,0)];
        dw_w      = (const float*)d_in[find_nth(in_sizes,n_in,12900,0)];
        dw_b      = (const float*)d_in[find_nth(in_sizes,n_in,516,0)];
        rpb       = (const float*)d_in[find_nth(in_sizes,n_in,5766,0)];
        rpi       = (const int*)  d_in[find_nth(in_sizes,n_in,65536,0)];
        aca_w  = (const float*)d_in[find_nth(in_sizes,n_in,44100,0)];
        winp_w = (const float*)d_in[find_nth(in_sizes,n_in,44100,1)];
        wv_w   = (const float*)d_in[find_nth(in_sizes,n_in,44100,2)];
        wk_w = (const float*)d_in[find_nth(in_sizes,n_in,4200,0)];
        wq_w = (const float*)d_in[find_nth(in_sizes,n_in,4200,1)];
        wk_b = (const float*)d_in[find_nth(in_sizes,n_in,20,0)];
        wq_b = (const float*)d_in[find_nth(in_sizes,n_in,20,1)];
        aca_b  = (const float*)d_in[find_nth(in_sizes,n_in,210,0)];
        b1     = (const float*)d_in[find_nth(in_sizes,n_in,210,1)];
        b2     = (const float*)d_in[find_nth(in_sizes,n_in,210,2)];
        fc2_b  = (const float*)d_in[find_nth(in_sizes,n_in,210,3)];
        g1     = (const float*)d_in[find_nth(in_sizes,n_in,210,4)];
        g2     = (const float*)d_in[find_nth(in_sizes,n_in,210,5)];
        winp_b = (const float*)d_in[find_nth(in_sizes,n_in,210,6)];
        wv_b   = (const float*)d_in[find_nth(in_sizes,n_in,210,7)];
        atd_scale = (const float*)d_in[find_nth(in_sizes,n_in,1,0)];
    }

    float *p_xn, *p_qkv, *p_x2, *p_xn2, *p_aca, *p_win, *p_hcat, *p_hcat2;
    cudaGetSymbolAddress((void**)&p_xn,    g_xn);
    cudaGetSymbolAddress((void**)&p_qkv,   g_qkv);
    cudaGetSymbolAddress((void**)&p_x2,    g_x2);
    cudaGetSymbolAddress((void**)&p_xn2,   g_xn2);
    cudaGetSymbolAddress((void**)&p_aca,   g_aca);
    cudaGetSymbolAddress((void**)&p_win,   g_win);
    cudaGetSymbolAddress((void**)&p_hcat,  g_hcat);
    cudaGetSymbolAddress((void**)&p_hcat2, g_hcat2);

    cudaFuncSetAttribute(atd_kernel,    cudaFuncAttributeMaxDynamicSharedMemorySize, ATD_SMEM);
    cudaFuncSetAttribute(acmsa_kernel,  cudaFuncAttributeMaxDynamicSharedMemorySize, ATT_SMEM);
    cudaFuncSetAttribute(winattn_kernel,cudaFuncAttributeMaxDynamicSharedMemorySize, ATT_SMEM);

    cudaStream_t s1;
    cudaStreamCreateWithFlags(&s1, cudaStreamNonBlocking);
    cudaEvent_t e0, eLN, eAux, eQKV, eW, eAtd, eTd;
    cudaEventCreateWithFlags(&e0,  cudaEventDisableTiming);
    cudaEventCreateWithFlags(&eLN, cudaEventDisableTiming);
    cudaEventCreateWithFlags(&eAux,cudaEventDisableTiming);
    cudaEventCreateWithFlags(&eQKV,cudaEventDisableTiming);
    cudaEventCreateWithFlags(&eW, cudaEventDisableTiming);
    cudaEventCreateWithFlags(&eAtd,cudaEventDisableTiming);
    cudaEventCreateWithFlags(&eTd, cudaEventDisableTiming);

    cudaEventRecord(e0, 0);
    cudaStreamWaitEvent(s1, e0, 0);

    biasprep_kernel<<<256,256,0,s1>>>(rpb, rpi);
    kv_kernel<<<BATCH*MTOK,256,0,s1>>>(td, wk_w,wk_b, wv_w,wv_b, fctd_w,fctd_b);

    ln_kernel<<<ROWS/8,256>>>(x, g1, b1, p_xn, ROWS);
    cudaEventRecord(eLN, 0);
    cudaStreamWaitEvent(s1, eLN, 0);
    sgemm_kernel<<<dim3(5,512),256>>>(p_xn,CDIM, wqkv_w,C3, wqkv_b, nullptr,0,
                                      p_qkv,C3, ROWS,C3,CDIM, 0);
    cudaEventRecord(eQKV, 0);

    qproj_kernel<<<ROWS/4,128,0,s1>>>(wq_w, wq_b);
    cudaEventRecord(eAux, s1);

    cudaStreamWaitEvent(s1, eQKV, 0);
    winattn_kernel<<<dim3(6,64,BATCH),256,ATT_SMEM,s1>>>(attn_mask);
    cudaEventRecord(eW, s1);

    cudaStreamWaitEvent(0, eAux, 0);
    atd_kernel<<<BATCH*256,256,ATD_SMEM>>>(x, atd_scale);
    cudaEventRecord(eAtd, 0);
    sort_kernel<<<BATCH,64>>>();
    acmsa_kernel<<<dim3(6,64,BATCH),256,ATT_SMEM>>>();

    cudaStreamWaitEvent(s1, eAtd, 0);
    tdgather_kernel<<<ROWS*96/256,256,0,s1>>>();
    cudaEventRecord(eTd, s1);

    cudaStreamWaitEvent(0, eW, 0);
    sgemm_dual<<<dim3(2,512),256>>>(p_aca, p_win, aca_w, winp_w, aca_b, winp_b, p_x2);

    ln_kernel<<<ROWS/8,256>>>(p_x2, g2, b2, p_xn2, ROWS);
    sgemm_kernel<<<dim3(4,512),256>>>(p_xn2,CDIM, fc1_w,MLPH, fc1_b, nullptr,0,
                                      p_hcat,HF2C, ROWS,MLPH,CDIM, 1);
    cudaStreamWaitEvent(0, eTd, 0);
    conv_kernel<<<dim3(17,256,BATCH),dim3(32,8)>>>(dw_w, dw_b);
    sgemm_kernel<<<dim3(2,512),256>>>(p_hcat2,HF2C, fc2_w,CDIM, fc2_b, p_x2,CDIM,
                                      (float*)d_out,CDIM, ROWS,CDIM,HF2C, 0);
}

// round 14
// speedup vs baseline: 1.0721x; 1.0481x over previous
#include <cuda_runtime.h>
#include <math.h>

#define BATCH 4
#define NTOK 16384
#define CDIM 210
#define C3   630
#define HDIM 35
#define MTOK 128
#define DRED 20
#define DTD 96
#define MLPH 420
#define HF2C 516
#define ROWS (BATCH*NTOK)
#define LOGM 4.852030263919617f

__device__ float g_xn  [ROWS*CDIM];
__device__ float g_qkv [(size_t)ROWS*C3];
__device__ float g_x2  [ROWS*CDIM];
__device__ float g_xn2 [ROWS*CDIM];
__device__ float g_q   [ROWS*DRED];
__device__ float g_kn  [BATCH*MTOK*DRED];
__device__ float g_v   [BATCH*MTOK*CDIM];
__device__ float g_ftd [BATCH*MTOK*DTD];
__device__ int   g_tkid[ROWS];
__device__ int   g_sidx[ROWS];
__device__ float g_aca [ROWS*CDIM];
__device__ float g_win [ROWS*CDIM];
__device__ float g_biasf[6*65536];
__device__ float g_hcat [(size_t)ROWS*HF2C];
__device__ float g_hcat2[(size_t)ROWS*HF2C];

__device__ __forceinline__ float gelu_exact(float v){
    return 0.5f*v*(1.0f+erff(v*0.7071067811865476f));
}

// ---------- LayerNorm: warp per row ----------
__global__ void ln_kernel(const float* __restrict__ in, const float* __restrict__ gam,
                          const float* __restrict__ bet, float* __restrict__ out, int rows)
{
    int warp = (blockIdx.x*blockDim.x + threadIdx.x) >> 5;
    int lane = threadIdx.x & 31;
    if (warp >= rows) return;
    const float* r = in + (size_t)warp*CDIM;
    float v[7]; float s = 0.f;
#pragma unroll
    for (int j=0;j<7;j++){ int k = lane + 32*j; v[j] = (k<CDIM)? r[k] : 0.f; s += v[j]; }
#pragma unroll
    for (int o=16;o;o>>=1) s += __shfl_xor_sync(0xffffffffu, s, o);
    float mu = s * (1.0f/CDIM);
    float vs = 0.f;
#pragma unroll
    for (int j=0;j<7;j++){ int k = lane + 32*j; if (k<CDIM){ float d = v[j]-mu; vs += d*d; } }
#pragma unroll
    for (int o=16;o;o>>=1) vs += __shfl_xor_sync(0xffffffffu, vs, o);
    float rstd = rsqrtf(vs*(1.0f/CDIM) + 1e-5f);
    float* o2 = out + (size_t)warp*CDIM;
#pragma unroll
    for (int j=0;j<7;j++){ int k = lane + 32*j; if (k<CDIM) o2[k] = (v[j]-mu)*rstd*gam[k] + bet[k]; }
}

// ---------- SGEMM: double-buffered 128x128x8, 8x8/thread (R11 proven core) ----------
__global__ __launch_bounds__(256,2) void sgemm_kernel(
        const float* __restrict__ A, int lda,
        const float* __restrict__ W, int ldw,
        const float* __restrict__ bias,
        const float* __restrict__ addp, int ldadd,
        float* __restrict__ C, int ldc,
        int Mr, int Nc, int K, int act)
{
    __shared__ float As[2][8][128];
    __shared__ float Bs[2][8][128];
    int tid = threadIdx.x;
    int tx = tid & 15, ty = tid >> 4;
    int row0 = blockIdx.y * 128, col0 = blockIdx.x * 128;
    float acc[8][8];
#pragma unroll
    for (int i=0;i<8;i++)
#pragma unroll
        for (int j=0;j<8;j++) acc[i][j]=0.f;
    int nk = (K+7)/8;
    float ra[4], rb[4];
    {
#pragma unroll
        for (int i=0;i<4;i++){
            int f = tid + i*256;
            int r = f>>3, kk = f&7;
            int gr = row0+r;
            ra[i] = (gr<Mr && kk<K)? A[(size_t)gr*lda + kk] : 0.f;
            int kb = f>>7, cb = f&127;
            int gc = col0+cb;
            rb[i] = (kb<K && gc<Nc)? W[(size_t)kb*ldw + gc] : 0.f;
        }
#pragma unroll
        for (int i=0;i<4;i++){
            int f = tid + i*256;
            As[0][f&7][f>>3] = ra[i];
            Bs[0][f>>7][f&127] = rb[i];
        }
    }
    __syncthreads();
    for (int kt=0; kt<nk; kt++){
        int cur = kt&1;
        if (kt+1 < nk){
            int k0 = (kt+1)*8;
#pragma unroll
            for (int i=0;i<4;i++){
                int f = tid + i*256;
                int r = f>>3, kk = f&7;
                int gr = row0+r, gk = k0+kk;
                ra[i] = (gr<Mr && gk<K)? A[(size_t)gr*lda + gk] : 0.f;
                int kb = f>>7, cb = f&127;
                int gc = col0+cb, gkb = k0+kb;
                rb[i] = (gkb<K && gc<Nc)? W[(size_t)gkb*ldw + gc] : 0.f;
            }
        }
#pragma unroll
        for (int kk=0;kk<8;kk++){
            float4 a0 = *(const float4*)&As[cur][kk][ty*8];
            float4 a1 = *(const float4*)&As[cur][kk][ty*8+4];
            float4 b0 = *(const float4*)&Bs[cur][kk][tx*8];
            float4 b1 = *(const float4*)&Bs[cur][kk][tx*8+4];
            float av[8] = {a0.x,a0.y,a0.z,a0.w,a1.x,a1.y,a1.z,a1.w};
            float bv[8] = {b0.x,b0.y,b0.z,b0.w,b1.x,b1.y,b1.z,b1.w};
#pragma unroll
            for (int i=0;i<8;i++)
#pragma unroll
                for (int j=0;j<8;j++) acc[i][j] += av[i]*bv[j];
        }
        if (kt+1 < nk){
            int nxt = cur^1;
#pragma unroll
            for (int i=0;i<4;i++){
                int f = tid + i*256;
                As[nxt][f&7][f>>3] = ra[i];
                Bs[nxt][f>>7][f&127] = rb[i];
            }
            __syncthreads();
        }
    }
    // fast path: full tile, no activation, no add, even ldc -> float2 stores
    if (row0+128<=Mr && col0+128<=Nc && act==0 && !addp && ((ldc&1)==0)){
#pragma unroll
        for (int i=0;i<8;i++){
            int r = row0 + ty*8 + i;
            float* cp = C + (size_t)r*ldc + col0 + tx*8;
#pragma unroll
            for (int j=0;j<4;j++){
                int c = col0 + tx*8 + 2*j;
                float2 v2 = make_float2(acc[i][2*j] + bias[c], acc[i][2*j+1] + bias[c+1]);
                *(float2*)(cp + 2*j) = v2;
            }
        }
        return;
    }
#pragma unroll
    for (int i=0;i<8;i++){
        int r = row0 + ty*8 + i;
        if (r >= Mr) continue;
#pragma unroll
        for (int j=0;j<8;j++){
            int c = col0 + tx*8 + j;
            if (c >= Nc) continue;
            float v = acc[i][j] + bias[c];
            if (act==1) v = gelu_exact(v);
            if (addp) v += addp[(size_t)r*ldadd + c];
            C[(size_t)r*ldc + c] = v;
        }
    }
}

// ---------- fused dual-projection GEMM: x2 += aca@W1 + win@W2 + b1 + b2 ----------
__global__ __launch_bounds__(256,2) void sgemm_dual(
        const float* __restrict__ A1, const float* __restrict__ A2,
        const float* __restrict__ W1, const float* __restrict__ W2,
        const float* __restrict__ b1v, const float* __restrict__ b2v,
        float* __restrict__ C)
{
    __shared__ float As[2][8][128];
    __shared__ float Bs[2][8][128];
    int tid = threadIdx.x;
    int tx = tid & 15, ty = tid >> 4;
    int row0 = blockIdx.y * 128, col0 = blockIdx.x * 128;
    float acc[8][8];
#pragma unroll
    for (int i=0;i<8;i++)
#pragma unroll
        for (int j=0;j<8;j++) acc[i][j]=0.f;
    const int K = 420, Nc = 210;
    int nk = (K+7)/8;
    float ra[4], rb[4];
    {
#pragma unroll
        for (int i=0;i<4;i++){
            int f = tid + i*256;
            int r = row0 + (f>>3), kk = f&7;
            ra[i] = A1[(size_t)r*210 + kk];
            int kb = f>>7, cb = f&127;
            int gc = col0+cb;
            rb[i] = (gc<Nc)? W1[kb*210 + gc] : 0.f;
        }
#pragma unroll
        for (int i=0;i<4;i++){
            int f = tid + i*256;
            As[0][f&7][f>>3] = ra[i];
            Bs[0][f>>7][f&127] = rb[i];
        }
    }
    __syncthreads();
    for (int kt=0; kt<nk; kt++){
        int cur = kt&1;
        if (kt+1 < nk){
            int k0 = (kt+1)*8;
#pragma unroll
            for (int i=0;i<4;i++){
                int f = tid + i*256;
                int r = row0 + (f>>3), gk = k0 + (f&7);
                float a = 0.f;
                if (gk < 210)       a = A1[(size_t)r*210 + gk];
                else if (gk < 420)  a = A2[(size_t)r*210 + gk-210];
                ra[i] = a;
                int gkb = k0 + (f>>7), cb = f&127;
                int gc = col0+cb;
                float b = 0.f;
                if (gc < Nc){
                    if (gkb < 210)      b = W1[gkb*210 + gc];
                    else if (gkb < 420) b = W2[(gkb-210)*210 + gc];
                }
                rb[i] = b;
            }
        }
#pragma unroll
        for (int kk=0;kk<8;kk++){
            float4 a0 = *(const float4*)&As[cur][kk][ty*8];
            float4 a1 = *(const float4*)&As[cur][kk][ty*8+4];
            float4 b0 = *(const float4*)&Bs[cur][kk][tx*8];
            float4 b1 = *(const float4*)&Bs[cur][kk][tx*8+4];
            float av[8] = {a0.x,a0.y,a0.z,a0.w,a1.x,a1.y,a1.z,a1.w};
            float bv[8] = {b0.x,b0.y,b0.z,b0.w,b1.x,b1.y,b1.z,b1.w};
#pragma unroll
            for (int i=0;i<8;i++)
#pragma unroll
                for (int j=0;j<8;j++) acc[i][j] += av[i]*bv[j];
        }
        if (kt+1 < nk){
            int nxt = cur^1;
#pragma unroll
            for (int i=0;i<4;i++){
                int f = tid + i*256;
                As[nxt][f&7][f>>3] = ra[i];
                Bs[nxt][f>>7][f&127] = rb[i];
            }
            __syncthreads();
        }
    }
#pragma unroll
    for (int i=0;i<8;i++){
        int r = row0 + ty*8 + i;
#pragma unroll
        for (int j=0;j<8;j++){
            int c = col0 + tx*8 + j;
            if (c >= Nc) continue;
            size_t idx = (size_t)r*210 + c;
            C[idx] = C[idx] + acc[i][j] + b1v[c] + b2v[c];
        }
    }
}

// ---------- q projection + l2norm: warp per row ----------
__global__ void qproj_kernel(const float* __restrict__ wq, const float* __restrict__ bq)
{
    __shared__ float s[4][CDIM];
    int w = threadIdx.x>>5, lane = threadIdx.x&31;
    int row = blockIdx.x*4 + w;
    const float* r = g_xn + (size_t)row*CDIM;
    for (int k=lane;k<CDIM;k+=32) s[w][k] = r[k];
    __syncwarp();
    float acc = 0.f;
    if (lane < DRED){
        acc = bq[lane];
        for (int k=0;k<CDIM;k++) acc += s[w][k]*wq[k*DRED+lane];
    }
    float sq = (lane<DRED)? acc*acc : 0.f;
#pragma unroll
    for (int o=16;o;o>>=1) sq += __shfl_xor_sync(0xffffffffu, sq, o);
    float den = fmaxf(sqrtf(sq), 1e-12f);
    if (lane < DRED) g_q[(size_t)row*DRED + lane] = acc/den;
}

// ---------- td projections ----------
__global__ void kv_kernel(const float* __restrict__ td,
                          const float* __restrict__ wk_w, const float* __restrict__ wk_b,
                          const float* __restrict__ wv_w, const float* __restrict__ wv_b,
                          const float* __restrict__ ftd_w, const float* __restrict__ ftd_b)
{
    __shared__ float tr[CDIM];
    __shared__ float ks_s[DRED];
    __shared__ float nrm_s;
    int rm = blockIdx.x;
    int b = rm >> 7, m = rm & 127;
    int t = threadIdx.x;
    const float* trow = td + (size_t)rm*CDIM;
    if (t < CDIM) tr[t] = trow[t];
    __syncthreads();
    if (t < CDIM){
        float a = wv_b[t];
        for (int k=0;k<CDIM;k++) a += tr[k]*wv_w[k*CDIM+t];
        g_v[(size_t)rm*CDIM + t] = a;
    }
    if (t < DTD){
        float a = ftd_b[t];
        for (int k=0;k<CDIM;k++) a += tr[k]*ftd_w[k*DTD+t];
        g_ftd[(size_t)rm*DTD + t] = a;
    }
    if (t < DRED){
        float a = wk_b[t];
        for (int k=0;k<CDIM;k++) a += tr[k]*wk_w[k*DRED+t];
        ks_s[t] = a;
    }
    __syncthreads();
    if (t==0){
        float s=0.f;
        for (int j=0;j<DRED;j++) s += ks_s[j]*ks_s[j];
        nrm_s = fmaxf(sqrtf(s), 1e-12f);
    }
    __syncthreads();
    if (t < DRED) g_kn[b*(MTOK*DRED) + t*MTOK + m] = ks_s[t]/nrm_s;
}

// ---------- fused ATD cross-attn (4 tokens/warp-iter) ----------
__global__ void atd_kernel(const float* __restrict__ x, const float* __restrict__ atd_scale)
{
    extern __shared__ float sm2[];
    float* vs  = sm2;
    float* knT = vs + MTOK*CDIM;
    float* pbuf= knT + DRED*MTOK;
    int tid = threadIdx.x, wid = tid>>5, lane = tid&31;
    int b  = blockIdx.x >> 8;
    int n0 = (blockIdx.x & 255) * 64;
    for (int f=tid; f<MTOK*CDIM; f+=256) vs[f]  = g_v [b*(MTOK*CDIM)+f];
    for (int f=tid; f<DRED*MTOK; f+=256) knT[f] = g_kn[b*(MTOK*DRED)+f];
    float sc = atd_scale[0];
    sc = 1.0f + fminf(fmaxf(sc,0.0f),3.0f)*LOGM;
    __syncthreads();
    for (int g=0; g<2; g++){
        int n = n0 + wid*8 + g*4;
        size_t rbase = (size_t)b*NTOK + n;
        float ql[4];
#pragma unroll
        for (int i=0;i<4;i++)
            ql[i] = (lane<DRED)? g_q[(rbase+i)*DRED + lane] : 0.f;
        float lg[4][4];
#pragma unroll
        for (int i=0;i<4;i++)
#pragma unroll
            for (int mm=0;mm<4;mm++) lg[i][mm]=0.f;
        for (int j=0;j<DRED;j++){
            float kv[4];
#pragma unroll
            for (int mm=0;mm<4;mm++) kv[mm] = knT[j*MTOK + lane + 32*mm];
#pragma unroll
            for (int i=0;i<4;i++){
                float qv = __shfl_sync(0xffffffffu, ql[i], j);
#pragma unroll
                for (int mm=0;mm<4;mm++) lg[i][mm] += qv*kv[mm];
            }
        }
#pragma unroll
        for (int i=0;i<4;i++){
#pragma unroll
            for (int mm=0;mm<4;mm++) lg[i][mm] *= sc;
            float bv = lg[i][0]; int bi = lane;
#pragma unroll
            for (int mm=1;mm<4;mm++){
                int m = lane+32*mm;
                if (lg[i][mm] > bv){ bv = lg[i][mm]; bi = m; }
            }
#pragma unroll
            for (int o=16;o;o>>=1){
                float ov = __shfl_xor_sync(0xffffffffu, bv, o);
                int   oi = __shfl_xor_sync(0xffffffffu, bi, o);
                if (ov > bv || (ov==bv && oi<bi)){ bv = ov; bi = oi; }
            }
            float sum = 0.f;
#pragma unroll
            for (int mm=0;mm<4;mm++){ lg[i][mm] = expf(lg[i][mm]-bv); sum += lg[i][mm]; }
#pragma unroll
            for (int o=16;o;o>>=1) sum += __shfl_xor_sync(0xffffffffu, sum, o);
            float inv = 1.0f/sum;
#pragma unroll
            for (int mm=0;mm<4;mm++) pbuf[(wid*4+i)*MTOK + lane + 32*mm] = lg[i][mm]*inv;
            if (lane==0) g_tkid[rbase+i] = bi;
        }
        __syncwarp();
        float a[4][7];
#pragma unroll
        for (int i=0;i<4;i++)
#pragma unroll
            for (int k=0;k<7;k++) a[i][k]=0.f;
#pragma unroll 2
        for (int m=0;m<MTOK;m++){
            float vv[7];
            const float* vrow = vs + m*CDIM;
#pragma unroll
            for (int k=0;k<6;k++) vv[k] = vrow[lane+32*k];
            vv[6] = (lane<18)? vrow[lane+192] : 0.f;
#pragma unroll
            for (int i=0;i<4;i++){
                float pm = pbuf[(wid*4+i)*MTOK + m];
#pragma unroll
                for (int k=0;k<7;k++) a[i][k] += pm*vv[k];
            }
        }
#pragma unroll
        for (int i=0;i<4;i++){
            const float* xr = x + (rbase+i)*CDIM;
            float* orow = g_x2 + (rbase+i)*CDIM;
#pragma unroll
            for (int k=0;k<6;k++) orow[lane+32*k] = xr[lane+32*k] + a[i][k];
            if (lane<18) orow[lane+192] = xr[lane+192] + a[i][6];
        }
        __syncwarp();
    }
}

// ---------- stable counting sort per batch ----------
__global__ void sort_kernel()
{
    __shared__ int cnt[64*128];
    __shared__ int binbase[128];
    int b = blockIdx.x, t = threadIdx.x;
    const int* key = g_tkid + b*NTOK;
    int* out = g_sidx + b*NTOK;
    for (int i=t;i<64*128;i+=64) cnt[i]=0;
    __syncthreads();
    for (int i=0;i<256;i++){ int k = key[t*256+i]; cnt[t*128+k]++; }
    __syncthreads();
    for (int bb=t; bb<128; bb+=64){
        int tot=0;
        for (int th=0; th<64; th++){ int v = cnt[th*128+bb]; cnt[th*128+bb]=tot; tot+=v; }
        binbase[bb]=tot;
    }
    __syncthreads();
    if (t==0){ int s=0; for (int bn=0;bn<128;bn++){ int v=binbase[bn]; binbase[bn]=s; s+=v; } }
    __syncthreads();
    for (int i=0;i<256;i++){
        int tok = t*256+i;
        int k = key[tok];
        int pos = binbase[k] + cnt[t*128+k]++;
        out[pos] = tok;
    }
}

// ---------- window bias precompute ----------
__global__ void biasprep_kernel(const float* __restrict__ rpb, const int* __restrict__ rpi)
{
    int i = blockIdx.x*256 + threadIdx.x;
    int r = rpi[i];
#pragma unroll
    for (int h=0;h<6;h++) g_biasf[h*65536 + i] = rpb[r*6 + h];
}

// ---------- attention core (stride 260, float4 PV) ----------
#define KSTR 260
#define ATT_SMEM ((2*35*KSTR + 8*4*256 + 256)*4)

__global__ __launch_bounds__(256,2) void acmsa_kernel()
{
    extern __shared__ float sm[];
    float* kT = sm;
    float* vT = sm + 35*KSTR;
    float* ps = sm + 2*35*KSTR;
    int*  tok = (int*)(sm + 2*35*KSTR + 8*4*256);
    int head = blockIdx.x, grp = blockIdx.y, b = blockIdx.z;
    int tid = threadIdx.x, wid = tid>>5, lane = tid&31;
    tok[tid] = g_sidx[b*NTOK + grp*256 + tid];
    __syncthreads();
    const float* qb = g_qkv + (size_t)b*NTOK*C3;
    for (int i=wid; i<256; i+=8){
        const float* p = qb + (size_t)tok[i]*C3 + head*HDIM;
        kT[lane*KSTR+i] = p[CDIM + lane];
        vT[lane*KSTR+i] = p[2*CDIM + lane];
        if (lane<3){
            kT[(lane+32)*KSTR+i] = p[CDIM + lane+32];
            vT[(lane+32)*KSTR+i] = p[2*CDIM + lane+32];
        }
    }
    __syncthreads();
    const float rs = 0.16903085094570331f;
    for (int it=0; it<8; it++){
        int qi0 = wid*32 + it*4;
        int tq[4]; float qd[4], qd2[4];
#pragma unroll
        for (int i=0;i<4;i++){
            tq[i] = tok[qi0+i];
            const float* qp = qb + (size_t)tq[i]*C3 + head*HDIM;
            qd[i]  = qp[lane];
            qd2[i] = (lane<3)? qp[lane+32] : 0.f;
        }
        float l[4][8];
#pragma unroll
        for (int i=0;i<4;i++)
#pragma unroll
            for (int j=0;j<8;j++) l[i][j]=0.f;
#pragma unroll 5
        for (int d=0; d<HDIM; d++){
            float kv[8];
#pragma unroll
            for (int j=0;j<8;j++) kv[j] = kT[d*KSTR + lane + 32*j];
#pragma unroll
            for (int i=0;i<4;i++){
                float qv = (d<32)? __shfl_sync(0xffffffffu, qd[i], d)
                                 : __shfl_sync(0xffffffffu, qd2[i], d-32);
#pragma unroll
                for (int j=0;j<8;j++) l[i][j] += qv*kv[j];
            }
        }
#pragma unroll
        for (int i=0;i<4;i++){
            float mx = -1e30f;
#pragma unroll
            for (int j=0;j<8;j++){ l[i][j] *= rs; mx = fmaxf(mx, l[i][j]); }
#pragma unroll
            for (int o=16;o;o>>=1) mx = fmaxf(mx, __shfl_xor_sync(0xffffffffu, mx, o));
            float sum = 0.f;
#pragma unroll
            for (int j=0;j<8;j++){ l[i][j] = expf(l[i][j]-mx); sum += l[i][j]; }
#pragma unroll
            for (int o=16;o;o>>=1) sum += __shfl_xor_sync(0xffffffffu, sum, o);
            float inv = 1.0f/sum;
#pragma unroll
            for (int j=0;j<8;j++) ps[(wid*4+i)*256 + lane + 32*j] = l[i][j]*inv;
        }
        __syncwarp();
        float a0[4]={0,0,0,0}, a1[4]={0,0,0,0};
        int d2ok = (lane<3);
#pragma unroll 2
        for (int m=0;m<256;m+=4){
            float4 vv  = *(const float4*)&vT[lane*KSTR+m];
            float4 vv2 = d2ok ? *(const float4*)&vT[(lane+32)*KSTR+m]
                              : make_float4(0.f,0.f,0.f,0.f);
#pragma unroll
            for (int i=0;i<4;i++){
                float4 pm = *(const float4*)&ps[(wid*4+i)*256+m];
                a0[i] += pm.x*vv.x + pm.y*vv.y + pm.z*vv.z + pm.w*vv.w;
                a1[i] += pm.x*vv2.x + pm.y*vv2.y + pm.z*vv2.z + pm.w*vv2.w;
            }
        }
#pragma unroll
        for (int i=0;i<4;i++){
            float* orow = g_aca + ((size_t)b*NTOK + tq[i])*CDIM + head*HDIM;
            orow[lane] = a0[i];
            if (lane<3) orow[lane+32] = a1[i];
        }
        __syncwarp();
    }
}

__global__ __launch_bounds__(256,2) void winattn_kernel(const float* __restrict__ mask)
{
    extern __shared__ float sm[];
    float* kT = sm;
    float* vT = sm + 35*KSTR;
    float* ps = sm + 2*35*KSTR;
    int*  tok = (int*)(sm + 2*35*KSTR + 8*4*256);
    int head = blockIdx.x, win = blockIdx.y, b = blockIdx.z;
    int wh = win>>3, ww = win&7;
    int tid = threadIdx.x, wid = tid>>5, lane = tid&31;
    {
        int i = tid;
        int y  = ((wh<<4) + (i>>4) + 8) & 127;
        int xq = ((ww<<4) + (i&15) + 8) & 127;
        tok[i] = y*128 + xq;
    }
    __syncthreads();
    const float* qb = g_qkv + (size_t)b*NTOK*C3;
    for (int i=wid; i<256; i+=8){
        const float* p = qb + (size_t)tok[i]*C3 + head*HDIM;
        kT[lane*KSTR+i] = p[CDIM + lane];
        vT[lane*KSTR+i] = p[2*CDIM + lane];
        if (lane<3){
            kT[(lane+32)*KSTR+i] = p[CDIM + lane+32];
            vT[(lane+32)*KSTR+i] = p[2*CDIM + lane+32];
        }
    }
    __syncthreads();
    const float rs = 0.16903085094570331f;
    for (int it=0; it<8; it++){
        int qi0 = wid*32 + it*4;
        int tq[4]; float qd[4], qd2[4];
#pragma unroll
        for (int i=0;i<4;i++){
            tq[i] = tok[qi0+i];
            const float* qp = qb + (size_t)tq[i]*C3 + head*HDIM;
            qd[i]  = qp[lane];
            qd2[i] = (lane<3)? qp[lane+32] : 0.f;
        }
        float l[4][8];
#pragma unroll
        for (int i=0;i<4;i++)
#pragma unroll
            for (int j=0;j<8;j++) l[i][j]=0.f;
#pragma unroll 5
        for (int d=0; d<HDIM; d++){
            float kv[8];
#pragma unroll
            for (int j=0;j<8;j++) kv[j] = kT[d*KSTR + lane + 32*j];
#pragma unroll
            for (int i=0;i<4;i++){
                float qv = (d<32)? __shfl_sync(0xffffffffu, qd[i], d)
                                 : __shfl_sync(0xffffffffu, qd2[i], d-32);
#pragma unroll
                for (int j=0;j<8;j++) l[i][j] += qv*kv[j];
            }
        }
#pragma unroll
        for (int i=0;i<4;i++){
            const float* brow = g_biasf + head*65536 + (qi0+i)*256;
            const float* mrow = mask + (size_t)win*65536 + (qi0+i)*256;
            float mx = -1e30f;
#pragma unroll
            for (int j=0;j<8;j++){
                l[i][j] = l[i][j]*rs + brow[lane+32*j] + mrow[lane+32*j];
                mx = fmaxf(mx, l[i][j]);
            }
#pragma unroll
            for (int o=16;o;o>>=1) mx = fmaxf(mx, __shfl_xor_sync(0xffffffffu, mx, o));
            float sum = 0.f;
#pragma unroll
            for (int j=0;j<8;j++){ l[i][j] = expf(l[i][j]-mx); sum += l[i][j]; }
#pragma unroll
            for (int o=16;o;o>>=1) sum += __shfl_xor_sync(0xffffffffu, sum, o);
            float inv = 1.0f/sum;
#pragma unroll
            for (int j=0;j<8;j++) ps[(wid*4+i)*256 + lane + 32*j] = l[i][j]*inv;
        }
        __syncwarp();
        float a0[4]={0,0,0,0}, a1[4]={0,0,0,0};
        int d2ok = (lane<3);
#pragma unroll 2
        for (int m=0;m<256;m+=4){
            float4 vv  = *(const float4*)&vT[lane*KSTR+m];
            float4 vv2 = d2ok ? *(const float4*)&vT[(lane+32)*KSTR+m]
                              : make_float4(0.f,0.f,0.f,0.f);
#pragma unroll
            for (int i=0;i<4;i++){
                float4 pm = *(const float4*)&ps[(wid*4+i)*256+m];
                a0[i] += pm.x*vv.x + pm.y*vv.y + pm.z*vv.z + pm.w*vv.w;
                a1[i] += pm.x*vv2.x + pm.y*vv2.y + pm.z*vv2.z + pm.w*vv2.w;
            }
        }
#pragma unroll
        for (int i=0;i<4;i++){
            float* orow = g_win + ((size_t)b*NTOK + tq[i])*CDIM + head*HDIM;
            orow[lane] = a0[i];
            if (lane<3) orow[lane+32] = a1[i];
        }
        __syncwarp();
    }
}

// ---------- gather td features into hcat[:,420:516] ----------
__global__ void tdgather_kernel()
{
    int i = blockIdx.x*256 + threadIdx.x;
    int row = i/96, j = i - row*96;
    int b = row >> 14;
    int tk = g_tkid[row];
    g_hcat[(size_t)row*HF2C + MLPH + j] = g_ftd[((b<<7)+tk)*DTD + j];
}

// ---------- depthwise 5x5 conv + gelu + residual ----------
__global__ __launch_bounds__(256) void conv_kernel(const float* __restrict__ dw_w,
                                                   const float* __restrict__ dw_b)
{
    __shared__ float s[144*32];
    __shared__ float wsm[32*25];
    int c0 = blockIdx.x*32;
    int tile = blockIdx.y;
    int ty0=(tile>>4)*8, tx0=(tile&15)*8;
    int b = blockIdx.z;
    int cx = threadIdx.x, py = threadIdx.y;
    int tid = py*32+cx;
    for (int f=tid; f<144*32; f+=256){
        int p=f>>5, ch=f&31;
        int gy=ty0-2+p/12, gx=tx0-2+p%12;
        int c=c0+ch;
        float v=0.f;
        if (gy>=0&&gy<128&&gx>=0&&gx<128&&c<HF2C)
            v = g_hcat[((size_t)(b*NTOK+gy*128+gx))*HF2C + c];
        s[f]=v;
    }
    for (int f=tid; f<32*25; f+=256){
        int ch=f/25, k=f-ch*25; int c=c0+ch;
        wsm[f] = (c<HF2C)? dw_w[c*25+k] : 0.f;
    }
    __syncthreads();
    int c = c0+cx;
    if (c>=HF2C) return;
    float bsv = dw_b[c];
    float wr[25];
#pragma unroll
    for (int k=0;k<25;k++) wr[k]=wsm[cx*25+k];
    for (int px=0;px<8;px++){
        float acc=0.f;
#pragma unroll
        for (int ky=0;ky<5;ky++)
#pragma unroll
            for (int kx=0;kx<5;kx++)
                acc += wr[ky*5+kx]*s[((py+ky)*12+px+kx)*32+cx];
        float center = s[((py+2)*12+px+2)*32+cx];
        float o = center + gelu_exact(acc+bsv);
        g_hcat2[((size_t)(b*NTOK+(ty0+py)*128+(tx0+px)))*HF2C + c] = o;
    }
}

#define ATD_SMEM ((MTOK*CDIM + DRED*MTOK + 8*4*MTOK)*4)

static int find_nth(const int* s, int n, int sz, int nth){
    int c=0;
    for (int i=0;i<n;i++){ if (s[i]==sz){ if (c==nth) return i; c++; } }
    return 0;
}

extern "C" void kernel_launch(void* const* d_in, const int* in_sizes, int n_in,
                              void* d_out, int out_size)
{
    const float *x,*td,*attn_mask,*g1,*b1,*g2,*b2,*wqkv_w,*wqkv_b,*wq_w,*wq_b;
    const float *wk_w,*wk_b,*wv_w,*wv_b,*atd_scale,*aca_w,*aca_b,*rpb,*winp_w,*winp_b;
    const float *fctd_w,*fctd_b,*fc1_w,*fc1_b,*dw_w,*dw_b,*fc2_w,*fc2_b;
    const int *rpi;

    if (in_sizes[0] == 13762560){
        bool sig = (in_sizes[2] > 1000000);
        x         = (const float*)d_in[0];
        td        = (const float*)d_in[1];
        attn_mask = (const float*)(sig ? d_in[2] : d_in[29]);
        int k = sig ? 3 : 2;
        g1 = (const float*)d_in[k+0];   b1 = (const float*)d_in[k+1];
        g2 = (const float*)d_in[k+2];   b2 = (const float*)d_in[k+3];
        wqkv_w = (const float*)d_in[k+4]; wqkv_b = (const float*)d_in[k+5];
        wq_w = (const float*)d_in[k+6];  wq_b = (const float*)d_in[k+7];
        wk_w = (const float*)d_in[k+8];  wk_b = (const float*)d_in[k+9];
        wv_w = (const float*)d_in[k+10]; wv_b = (const float*)d_in[k+11];
        atd_scale = (const float*)d_in[k+12];
        aca_w = (const float*)d_in[k+13]; aca_b = (const float*)d_in[k+14];
        rpb = (const float*)d_in[k+15];
        winp_w = (const float*)d_in[k+16]; winp_b = (const float*)d_in[k+17];
        fctd_w = (const float*)d_in[k+18]; fctd_b = (const float*)d_in[k+19];
        fc1_w = (const float*)d_in[k+20]; fc1_b = (const float*)d_in[k+21];
        dw_w = (const float*)d_in[k+22];  dw_b = (const float*)d_in[k+23];
        fc2_w = (const float*)d_in[k+24]; fc2_b = (const float*)d_in[k+25];
        rpi = (const int*)d_in[k+26];
    } else {
        x         = (const float*)d_in[find_nth(in_sizes,n_in,13762560,0)];
        td        = (const float*)d_in[find_nth(in_sizes,n_in,107520,0)];
        attn_mask = (const float*)d_in[find_nth(in_sizes,n_in,4194304,0)];
        wqkv_w    = (const float*)d_in[find_nth(in_sizes,n_in,132300,0)];
        wqkv_b    = (const float*)d_in[find_nth(in_sizes,n_in,630,0)];
        fc2_w     = (const float*)d_in[find_nth(in_sizes,n_in,108360,0)];
        fc1_w     = (const float*)d_in[find_nth(in_sizes,n_in,88200,0)];
        fc1_b     = (const float*)d_in[find_nth(in_sizes,n_in,420,0)];
        fctd_w    = (const float*)d_in[find_nth(in_sizes,n_in,20160,0)];
        fctd_b    = (const float*)d_in[find_nth(in_sizes,n_in,96,0)];
        dw_w      = (const float*)d_in[find_nth(in_sizes,n_in,12900,0)];
        dw_b      = (const float*)d_in[find_nth(in_sizes,n_in,516,0)];
        rpb       = (const float*)d_in[find_nth(in_sizes,n_in,5766,0)];
        rpi       = (const int*)  d_in[find_nth(in_sizes,n_in,65536,0)];
        aca_w  = (const float*)d_in[find_nth(in_sizes,n_in,44100,0)];
        winp_w = (const float*)d_in[find_nth(in_sizes,n_in,44100,1)];
        wv_w   = (const float*)d_in[find_nth(in_sizes,n_in,44100,2)];
        wk_w = (const float*)d_in[find_nth(in_sizes,n_in,4200,0)];
        wq_w = (const float*)d_in[find_nth(in_sizes,n_in,4200,1)];
        wk_b = (const float*)d_in[find_nth(in_sizes,n_in,20,0)];
        wq_b = (const float*)d_in[find_nth(in_sizes,n_in,20,1)];
        aca_b  = (const float*)d_in[find_nth(in_sizes,n_in,210,0)];
        b1     = (const float*)d_in[find_nth(in_sizes,n_in,210,1)];
        b2     = (const float*)d_in[find_nth(in_sizes,n_in,210,2)];
        fc2_b  = (const float*)d_in[find_nth(in_sizes,n_in,210,3)];
        g1     = (const float*)d_in[find_nth(in_sizes,n_in,210,4)];
        g2     = (const float*)d_in[find_nth(in_sizes,n_in,210,5)];
        winp_b = (const float*)d_in[find_nth(in_sizes,n_in,210,6)];
        wv_b   = (const float*)d_in[find_nth(in_sizes,n_in,210,7)];
        atd_scale = (const float*)d_in[find_nth(in_sizes,n_in,1,0)];
    }

    float *p_xn, *p_qkv, *p_x2, *p_xn2, *p_aca, *p_win, *p_hcat, *p_hcat2;
    cudaGetSymbolAddress((void**)&p_xn,    g_xn);
    cudaGetSymbolAddress((void**)&p_qkv,   g_qkv);
    cudaGetSymbolAddress((void**)&p_x2,    g_x2);
    cudaGetSymbolAddress((void**)&p_xn2,   g_xn2);
    cudaGetSymbolAddress((void**)&p_aca,   g_aca);
    cudaGetSymbolAddress((void**)&p_win,   g_win);
    cudaGetSymbolAddress((void**)&p_hcat,  g_hcat);
    cudaGetSymbolAddress((void**)&p_hcat2, g_hcat2);

    cudaFuncSetAttribute(atd_kernel,    cudaFuncAttributeMaxDynamicSharedMemorySize, ATD_SMEM);
    cudaFuncSetAttribute(acmsa_kernel,  cudaFuncAttributeMaxDynamicSharedMemorySize, ATT_SMEM);
    cudaFuncSetAttribute(winattn_kernel,cudaFuncAttributeMaxDynamicSharedMemorySize, ATT_SMEM);

    cudaStream_t s1;
    cudaStreamCreateWithFlags(&s1, cudaStreamNonBlocking);
    cudaEvent_t e0, eLN, eQKV, eSort, eW, eTd;
    cudaEventCreateWithFlags(&e0,   cudaEventDisableTiming);
    cudaEventCreateWithFlags(&eLN,  cudaEventDisableTiming);
    cudaEventCreateWithFlags(&eQKV, cudaEventDisableTiming);
    cudaEventCreateWithFlags(&eSort,cudaEventDisableTiming);
    cudaEventCreateWithFlags(&eW,   cudaEventDisableTiming);
    cudaEventCreateWithFlags(&eTd,  cudaEventDisableTiming);

    // fork s1 from the (captured) legacy stream
    cudaEventRecord(e0, 0);
    cudaStreamWaitEvent(s1, e0, 0);

    // s1: independent prep
    biasprep_kernel<<<256,256,0,s1>>>(rpb, rpi);
    kv_kernel<<<BATCH*MTOK,256,0,s1>>>(td, wk_w,wk_b, wv_w,wv_b, fctd_w,fctd_b);

    // s0: layernorm; then big qkv GEMM
    ln_kernel<<<ROWS/8,256>>>(x, g1, b1, p_xn, ROWS);
    cudaEventRecord(eLN, 0);
    cudaStreamWaitEvent(s1, eLN, 0);
    sgemm_kernel<<<dim3(5,512),256>>>(p_xn,CDIM, wqkv_w,C3, wqkv_b, nullptr,0,
                                      p_qkv,C3, ROWS,C3,CDIM, 0);
    cudaEventRecord(eQKV, 0);

    // s1: ATD chain fully concurrent with qkv GEMM (no qkv dependency)
    qproj_kernel<<<ROWS/4,128,0,s1>>>(wq_w, wq_b);
    atd_kernel<<<BATCH*256,256,ATD_SMEM,s1>>>(x, atd_scale);
    sort_kernel<<<BATCH,64,0,s1>>>();
    cudaEventRecord(eSort, s1);
    tdgather_kernel<<<ROWS*96/256,256,0,s1>>>();
    cudaEventRecord(eTd, s1);

    // s1: window attention after qkv
    cudaStreamWaitEvent(s1, eQKV, 0);
    winattn_kernel<<<dim3(6,64,BATCH),256,ATT_SMEM,s1>>>(attn_mask);
    cudaEventRecord(eW, s1);

    // s0: grouped attention after sort (qkv already done on s0)
    cudaStreamWaitEvent(0, eSort, 0);
    acmsa_kernel<<<dim3(6,64,BATCH),256,ATT_SMEM>>>();

    // join, fused dual projection: x2 += aca@Wa + win@Ww + ba + bw
    cudaStreamWaitEvent(0, eW, 0);
    sgemm_dual<<<dim3(2,512),256>>>(p_aca, p_win, aca_w, winp_w, aca_b, winp_b, p_x2);

    ln_kernel<<<ROWS/8,256>>>(p_x2, g2, b2, p_xn2, ROWS);
    sgemm_kernel<<<dim3(4,512),256>>>(p_xn2,CDIM, fc1_w,MLPH, fc1_b, nullptr,0,
                                      p_hcat,HF2C, ROWS,MLPH,CDIM, 1);
    cudaStreamWaitEvent(0, eTd, 0);
    conv_kernel<<<dim3(17,256,BATCH),dim3(32,8)>>>(dw_w, dw_b);
    sgemm_kernel<<<dim3(2,512),256>>>(p_hcat2,HF2C, fc2_w,CDIM, fc2_b, p_x2,CDIM,
                                      (float*)d_out,CDIM, ROWS,CDIM,HF2C, 0);
}

// round 15
// speedup vs baseline: 1.0779x; 1.0055x over previous
#include <cuda_runtime.h>
#include <math.h>

#define BATCH 4
#define NTOK 16384
#define CDIM 210
#define C3   630
#define HDIM 35
#define MTOK 128
#define DRED 20
#define DTD 96
#define MLPH 420
#define HF2C 516
#define ROWS (BATCH*NTOK)
#define LOGM 4.852030263919617f

__device__ float g_xn  [ROWS*CDIM];
__device__ float g_qkv [(size_t)ROWS*C3];
__device__ float g_x2  [ROWS*CDIM];
__device__ float g_xn2 [ROWS*CDIM];
__device__ float g_q   [ROWS*DRED];
__device__ float g_kn  [BATCH*MTOK*DRED];
__device__ float g_v   [BATCH*MTOK*CDIM];
__device__ float g_ftd [BATCH*MTOK*DTD];
__device__ int   g_tkid[ROWS];
__device__ int   g_sidx[ROWS];
__device__ float g_aca [ROWS*CDIM];
__device__ float g_win [ROWS*CDIM];
__device__ float g_biasf[6*65536];
__device__ float g_hcat [(size_t)ROWS*HF2C];
__device__ float g_hcat2[(size_t)ROWS*HF2C];

__device__ __forceinline__ float gelu_exact(float v){
    return 0.5f*v*(1.0f+erff(v*0.7071067811865476f));
}

// ---------- LayerNorm: warp per row ----------
__global__ void ln_kernel(const float* __restrict__ in, const float* __restrict__ gam,
                          const float* __restrict__ bet, float* __restrict__ out, int rows)
{
    int warp = (blockIdx.x*blockDim.x + threadIdx.x) >> 5;
    int lane = threadIdx.x & 31;
    if (warp >= rows) return;
    const float* r = in + (size_t)warp*CDIM;
    float v[7]; float s = 0.f;
#pragma unroll
    for (int j=0;j<7;j++){ int k = lane + 32*j; v[j] = (k<CDIM)? r[k] : 0.f; s += v[j]; }
#pragma unroll
    for (int o=16;o;o>>=1) s += __shfl_xor_sync(0xffffffffu, s, o);
    float mu = s * (1.0f/CDIM);
    float vs = 0.f;
#pragma unroll
    for (int j=0;j<7;j++){ int k = lane + 32*j; if (k<CDIM){ float d = v[j]-mu; vs += d*d; } }
#pragma unroll
    for (int o=16;o;o>>=1) vs += __shfl_xor_sync(0xffffffffu, vs, o);
    float rstd = rsqrtf(vs*(1.0f/CDIM) + 1e-5f);
    float* o2 = out + (size_t)warp*CDIM;
#pragma unroll
    for (int j=0;j<7;j++){ int k = lane + 32*j; if (k<CDIM) o2[k] = (v[j]-mu)*rstd*gam[k] + bet[k]; }
}

// ---------- SGEMM: double-buffered 128x128x8, 8x8/thread ----------
__global__ __launch_bounds__(256,2) void sgemm_kernel(
        const float* __restrict__ A, int lda,
        const float* __restrict__ W, int ldw,
        const float* __restrict__ bias,
        const float* __restrict__ addp, int ldadd,
        float* __restrict__ C, int ldc,
        int Mr, int Nc, int K, int act)
{
    __shared__ float As[2][8][128];
    __shared__ float Bs[2][8][128];
    int tid = threadIdx.x;
    int tx = tid & 15, ty = tid >> 4;
    int row0 = blockIdx.y * 128, col0 = blockIdx.x * 128;
    float acc[8][8];
#pragma unroll
    for (int i=0;i<8;i++)
#pragma unroll
        for (int j=0;j<8;j++) acc[i][j]=0.f;
    int nk = (K+7)/8;
    float ra[4], rb[4];
    {
#pragma unroll
        for (int i=0;i<4;i++){
            int f = tid + i*256;
            int r = f>>3, kk = f&7;
            int gr = row0+r;
            ra[i] = (gr<Mr && kk<K)? A[(size_t)gr*lda + kk] : 0.f;
            int kb = f>>7, cb = f&127;
            int gc = col0+cb;
            rb[i] = (kb<K && gc<Nc)? W[(size_t)kb*ldw + gc] : 0.f;
        }
#pragma unroll
        for (int i=0;i<4;i++){
            int f = tid + i*256;
            As[0][f&7][f>>3] = ra[i];
            Bs[0][f>>7][f&127] = rb[i];
        }
    }
    __syncthreads();
    for (int kt=0; kt<nk; kt++){
        int cur = kt&1;
        if (kt+1 < nk){
            int k0 = (kt+1)*8;
#pragma unroll
            for (int i=0;i<4;i++){
                int f = tid + i*256;
                int r = f>>3, kk = f&7;
                int gr = row0+r, gk = k0+kk;
                ra[i] = (gr<Mr && gk<K)? A[(size_t)gr*lda + gk] : 0.f;
                int kb = f>>7, cb = f&127;
                int gc = col0+cb, gkb = k0+kb;
                rb[i] = (gkb<K && gc<Nc)? W[(size_t)gkb*ldw + gc] : 0.f;
            }
        }
#pragma unroll
        for (int kk=0;kk<8;kk++){
            float4 a0 = *(const float4*)&As[cur][kk][ty*8];
            float4 a1 = *(const float4*)&As[cur][kk][ty*8+4];
            float4 b0 = *(const float4*)&Bs[cur][kk][tx*8];
            float4 b1 = *(const float4*)&Bs[cur][kk][tx*8+4];
            float av[8] = {a0.x,a0.y,a0.z,a0.w,a1.x,a1.y,a1.z,a1.w};
            float bv[8] = {b0.x,b0.y,b0.z,b0.w,b1.x,b1.y,b1.z,b1.w};
#pragma unroll
            for (int i=0;i<8;i++)
#pragma unroll
                for (int j=0;j<8;j++) acc[i][j] += av[i]*bv[j];
        }
        if (kt+1 < nk){
            int nxt = cur^1;
#pragma unroll
            for (int i=0;i<4;i++){
                int f = tid + i*256;
                As[nxt][f&7][f>>3] = ra[i];
                Bs[nxt][f>>7][f&127] = rb[i];
            }
            __syncthreads();
        }
    }
    if (row0+128<=Mr && col0+128<=Nc && act==0 && !addp && ((ldc&1)==0)){
#pragma unroll
        for (int i=0;i<8;i++){
            int r = row0 + ty*8 + i;
            float* cp = C + (size_t)r*ldc + col0 + tx*8;
#pragma unroll
            for (int j=0;j<4;j++){
                int c = col0 + tx*8 + 2*j;
                float2 v2 = make_float2(acc[i][2*j] + bias[c], acc[i][2*j+1] + bias[c+1]);
                *(float2*)(cp + 2*j) = v2;
            }
        }
        return;
    }
#pragma unroll
    for (int i=0;i<8;i++){
        int r = row0 + ty*8 + i;
        if (r >= Mr) continue;
#pragma unroll
        for (int j=0;j<8;j++){
            int c = col0 + tx*8 + j;
            if (c >= Nc) continue;
            float v = acc[i][j] + bias[c];
            if (act==1) v = gelu_exact(v);
            if (addp) v += addp[(size_t)r*ldadd + c];
            C[(size_t)r*ldc + c] = v;
        }
    }
}

// ---------- fused dual-projection GEMM: x2 += aca@W1 + win@W2 + b1 + b2 ----------
__global__ __launch_bounds__(256,2) void sgemm_dual(
        const float* __restrict__ A1, const float* __restrict__ A2,
        const float* __restrict__ W1, const float* __restrict__ W2,
        const float* __restrict__ b1v, const float* __restrict__ b2v,
        float* __restrict__ C)
{
    __shared__ float As[2][8][128];
    __shared__ float Bs[2][8][128];
    int tid = threadIdx.x;
    int tx = tid & 15, ty = tid >> 4;
    int row0 = blockIdx.y * 128, col0 = blockIdx.x * 128;
    float acc[8][8];
#pragma unroll
    for (int i=0;i<8;i++)
#pragma unroll
        for (int j=0;j<8;j++) acc[i][j]=0.f;
    const int K = 420, Nc = 210;
    int nk = (K+7)/8;
    float ra[4], rb[4];
    {
#pragma unroll
        for (int i=0;i<4;i++){
            int f = tid + i*256;
            int r = row0 + (f>>3), kk = f&7;
            ra[i] = A1[(size_t)r*210 + kk];
            int kb = f>>7, cb = f&127;
            int gc = col0+cb;
            rb[i] = (gc<Nc)? W1[kb*210 + gc] : 0.f;
        }
#pragma unroll
        for (int i=0;i<4;i++){
            int f = tid + i*256;
            As[0][f&7][f>>3] = ra[i];
            Bs[0][f>>7][f&127] = rb[i];
        }
    }
    __syncthreads();
    for (int kt=0; kt<nk; kt++){
        int cur = kt&1;
        if (kt+1 < nk){
            int k0 = (kt+1)*8;
#pragma unroll
            for (int i=0;i<4;i++){
                int f = tid + i*256;
                int r = row0 + (f>>3), gk = k0 + (f&7);
                float a = 0.f;
                if (gk < 210)       a = A1[(size_t)r*210 + gk];
                else if (gk < 420)  a = A2[(size_t)r*210 + gk-210];
                ra[i] = a;
                int gkb = k0 + (f>>7), cb = f&127;
                int gc = col0+cb;
                float b = 0.f;
                if (gc < Nc){
                    if (gkb < 210)      b = W1[gkb*210 + gc];
                    else if (gkb < 420) b = W2[(gkb-210)*210 + gc];
                }
                rb[i] = b;
            }
        }
#pragma unroll
        for (int kk=0;kk<8;kk++){
            float4 a0 = *(const float4*)&As[cur][kk][ty*8];
            float4 a1 = *(const float4*)&As[cur][kk][ty*8+4];
            float4 b0 = *(const float4*)&Bs[cur][kk][tx*8];
            float4 b1 = *(const float4*)&Bs[cur][kk][tx*8+4];
            float av[8] = {a0.x,a0.y,a0.z,a0.w,a1.x,a1.y,a1.z,a1.w};
            float bv[8] = {b0.x,b0.y,b0.z,b0.w,b1.x,b1.y,b1.z,b1.w};
#pragma unroll
            for (int i=0;i<8;i++)
#pragma unroll
                for (int j=0;j<8;j++) acc[i][j] += av[i]*bv[j];
        }
        if (kt+1 < nk){
            int nxt = cur^1;
#pragma unroll
            for (int i=0;i<4;i++){
                int f = tid + i*256;
                As[nxt][f&7][f>>3] = ra[i];
                Bs[nxt][f>>7][f&127] = rb[i];
            }
            __syncthreads();
        }
    }
#pragma unroll
    for (int i=0;i<8;i++){
        int r = row0 + ty*8 + i;
#pragma unroll
        for (int j=0;j<8;j++){
            int c = col0 + tx*8 + j;
            if (c >= Nc) continue;
            size_t idx = (size_t)r*210 + c;
            C[idx] = C[idx] + acc[i][j] + b1v[c] + b2v[c];
        }
    }
}

// ---------- q projection + l2norm: warp per row ----------
__global__ void qproj_kernel(const float* __restrict__ wq, const float* __restrict__ bq)
{
    __shared__ float s[4][CDIM];
    int w = threadIdx.x>>5, lane = threadIdx.x&31;
    int row = blockIdx.x*4 + w;
    const float* r = g_xn + (size_t)row*CDIM;
    for (int k=lane;k<CDIM;k+=32) s[w][k] = r[k];
    __syncwarp();
    float acc = 0.f;
    if (lane < DRED){
        acc = bq[lane];
        for (int k=0;k<CDIM;k++) acc += s[w][k]*wq[k*DRED+lane];
    }
    float sq = (lane<DRED)? acc*acc : 0.f;
#pragma unroll
    for (int o=16;o;o>>=1) sq += __shfl_xor_sync(0xffffffffu, sq, o);
    float den = fmaxf(sqrtf(sq), 1e-12f);
    if (lane < DRED) g_q[(size_t)row*DRED + lane] = acc/den;
}

// ---------- td projections ----------
__global__ void kv_kernel(const float* __restrict__ td,
                          const float* __restrict__ wk_w, const float* __restrict__ wk_b,
                          const float* __restrict__ wv_w, const float* __restrict__ wv_b,
                          const float* __restrict__ ftd_w, const float* __restrict__ ftd_b)
{
    __shared__ float tr[CDIM];
    __shared__ float ks_s[DRED];
    __shared__ float nrm_s;
    int rm = blockIdx.x;
    int b = rm >> 7, m = rm & 127;
    int t = threadIdx.x;
    const float* trow = td + (size_t)rm*CDIM;
    if (t < CDIM) tr[t] = trow[t];
    __syncthreads();
    if (t < CDIM){
        float a = wv_b[t];
        for (int k=0;k<CDIM;k++) a += tr[k]*wv_w[k*CDIM+t];
        g_v[(size_t)rm*CDIM + t] = a;
    }
    if (t < DTD){
        float a = ftd_b[t];
        for (int k=0;k<CDIM;k++) a += tr[k]*ftd_w[k*DTD+t];
        g_ftd[(size_t)rm*DTD + t] = a;
    }
    if (t < DRED){
        float a = wk_b[t];
        for (int k=0;k<CDIM;k++) a += tr[k]*wk_w[k*DRED+t];
        ks_s[t] = a;
    }
    __syncthreads();
    if (t==0){
        float s=0.f;
        for (int j=0;j<DRED;j++) s += ks_s[j]*ks_s[j];
        nrm_s = fmaxf(sqrtf(s), 1e-12f);
    }
    __syncthreads();
    if (t < DRED) g_kn[b*(MTOK*DRED) + t*MTOK + m] = ks_s[t]/nrm_s;
}

// ---------- fused ATD cross-attn (4 tokens/warp-iter) ----------
__global__ void atd_kernel(const float* __restrict__ x, const float* __restrict__ atd_scale)
{
    extern __shared__ float sm2[];
    float* vs  = sm2;
    float* knT = vs + MTOK*CDIM;
    float* pbuf= knT + DRED*MTOK;
    int tid = threadIdx.x, wid = tid>>5, lane = tid&31;
    int b  = blockIdx.x >> 8;
    int n0 = (blockIdx.x & 255) * 64;
    for (int f=tid; f<MTOK*CDIM; f+=256) vs[f]  = g_v [b*(MTOK*CDIM)+f];
    for (int f=tid; f<DRED*MTOK; f+=256) knT[f] = g_kn[b*(MTOK*DRED)+f];
    float sc = atd_scale[0];
    sc = 1.0f + fminf(fmaxf(sc,0.0f),3.0f)*LOGM;
    __syncthreads();
    for (int g=0; g<2; g++){
        int n = n0 + wid*8 + g*4;
        size_t rbase = (size_t)b*NTOK + n;
        float ql[4];
#pragma unroll
        for (int i=0;i<4;i++)
            ql[i] = (lane<DRED)? g_q[(rbase+i)*DRED + lane] : 0.f;
        float lg[4][4];
#pragma unroll
        for (int i=0;i<4;i++)
#pragma unroll
            for (int mm=0;mm<4;mm++) lg[i][mm]=0.f;
        for (int j=0;j<DRED;j++){
            float kv[4];
#pragma unroll
            for (int mm=0;mm<4;mm++) kv[mm] = knT[j*MTOK + lane + 32*mm];
#pragma unroll
            for (int i=0;i<4;i++){
                float qv = __shfl_sync(0xffffffffu, ql[i], j);
#pragma unroll
                for (int mm=0;mm<4;mm++) lg[i][mm] += qv*kv[mm];
            }
        }
#pragma unroll
        for (int i=0;i<4;i++){
#pragma unroll
            for (int mm=0;mm<4;mm++) lg[i][mm] *= sc;
            float bv = lg[i][0]; int bi = lane;
#pragma unroll
            for (int mm=1;mm<4;mm++){
                int m = lane+32*mm;
                if (lg[i][mm] > bv){ bv = lg[i][mm]; bi = m; }
            }
#pragma unroll
            for (int o=16;o;o>>=1){
                float ov = __shfl_xor_sync(0xffffffffu, bv, o);
                int   oi = __shfl_xor_sync(0xffffffffu, bi, o);
                if (ov > bv || (ov==bv && oi<bi)){ bv = ov; bi = oi; }
            }
            float sum = 0.f;
#pragma unroll
            for (int mm=0;mm<4;mm++){ lg[i][mm] = expf(lg[i][mm]-bv); sum += lg[i][mm]; }
#pragma unroll
            for (int o=16;o;o>>=1) sum += __shfl_xor_sync(0xffffffffu, sum, o);
            float inv = 1.0f/sum;
#pragma unroll
            for (int mm=0;mm<4;mm++) pbuf[(wid*4+i)*MTOK + lane + 32*mm] = lg[i][mm]*inv;
            if (lane==0) g_tkid[rbase+i] = bi;
        }
        __syncwarp();
        float a[4][7];
#pragma unroll
        for (int i=0;i<4;i++)
#pragma unroll
            for (int k=0;k<7;k++) a[i][k]=0.f;
#pragma unroll 2
        for (int m=0;m<MTOK;m++){
            float vv[7];
            const float* vrow = vs + m*CDIM;
#pragma unroll
            for (int k=0;k<6;k++) vv[k] = vrow[lane+32*k];
            vv[6] = (lane<18)? vrow[lane+192] : 0.f;
#pragma unroll
            for (int i=0;i<4;i++){
                float pm = pbuf[(wid*4+i)*MTOK + m];
#pragma unroll
                for (int k=0;k<7;k++) a[i][k] += pm*vv[k];
            }
        }
#pragma unroll
        for (int i=0;i<4;i++){
            const float* xr = x + (rbase+i)*CDIM;
            float* orow = g_x2 + (rbase+i)*CDIM;
#pragma unroll
            for (int k=0;k<6;k++) orow[lane+32*k] = xr[lane+32*k] + a[i][k];
            if (lane<18) orow[lane+192] = xr[lane+192] + a[i][6];
        }
        __syncwarp();
    }
}

// ---------- stable counting sort per batch ----------
__global__ void sort_kernel()
{
    __shared__ int cnt[64*128];
    __shared__ int binbase[128];
    int b = blockIdx.x, t = threadIdx.x;
    const int* key = g_tkid + b*NTOK;
    int* out = g_sidx + b*NTOK;
    for (int i=t;i<64*128;i+=64) cnt[i]=0;
    __syncthreads();
    for (int i=0;i<256;i++){ int k = key[t*256+i]; cnt[t*128+k]++; }
    __syncthreads();
    for (int bb=t; bb<128; bb+=64){
        int tot=0;
        for (int th=0; th<64; th++){ int v = cnt[th*128+bb]; cnt[th*128+bb]=tot; tot+=v; }
        binbase[bb]=tot;
    }
    __syncthreads();
    if (t==0){ int s=0; for (int bn=0;bn<128;bn++){ int v=binbase[bn]; binbase[bn]=s; s+=v; } }
    __syncthreads();
    for (int i=0;i<256;i++){
        int tok = t*256+i;
        int k = key[tok];
        int pos = binbase[k] + cnt[t*128+k]++;
        out[pos] = tok;
    }
}

// ---------- window bias precompute ----------
__global__ void biasprep_kernel(const float* __restrict__ rpb, const int* __restrict__ rpi)
{
    int i = blockIdx.x*256 + threadIdx.x;
    int r = rpi[i];
#pragma unroll
    for (int h=0;h<6;h++) g_biasf[h*65536 + i] = rpb[r*6 + h];
}

// ---------- combined attention (grouped + window), 4 queries/warp-iter ----------
#define KSTR 260
#define ATT_SMEM ((2*35*KSTR + 8*4*256 + 256)*4)

__global__ __launch_bounds__(256,2) void attn_kernel(const float* __restrict__ mask)
{
    extern __shared__ float sm[];
    float* kT = sm;
    float* vT = sm + 35*KSTR;
    float* ps = sm + 2*35*KSTR;
    int*  tok = (int*)(sm + 2*35*KSTR + 8*4*256);
    int hsel = blockIdx.x;                 // 0..11
    int iswin = (hsel >= 6);
    int head = iswin ? (hsel-6) : hsel;
    int grp = blockIdx.y, b = blockIdx.z;
    int tid = threadIdx.x, wid = tid>>5, lane = tid&31;
    if (iswin){
        int wh = grp>>3, ww = grp&7;
        int y  = ((wh<<4) + (tid>>4) + 8) & 127;
        int xq = ((ww<<4) + (tid&15) + 8) & 127;
        tok[tid] = y*128 + xq;
    } else {
        tok[tid] = g_sidx[b*NTOK + grp*256 + tid];
    }
    __syncthreads();
    const float* qb = g_qkv + (size_t)b*NTOK*C3;
    for (int i=wid; i<256; i+=8){
        const float* p = qb + (size_t)tok[i]*C3 + head*HDIM;
        kT[lane*KSTR+i] = p[CDIM + lane];
        vT[lane*KSTR+i] = p[2*CDIM + lane];
        if (lane<3){
            kT[(lane+32)*KSTR+i] = p[CDIM + lane+32];
            vT[(lane+32)*KSTR+i] = p[2*CDIM + lane+32];
        }
    }
    __syncthreads();
    const float rs = 0.16903085094570331f;
    for (int it=0; it<8; it++){
        int qi0 = wid*32 + it*4;
        int tq[4]; float qd[4], qd2[4];
#pragma unroll
        for (int i=0;i<4;i++){
            tq[i] = tok[qi0+i];
            const float* qp = qb + (size_t)tq[i]*C3 + head*HDIM;
            qd[i]  = qp[lane];
            qd2[i] = (lane<3)? qp[lane+32] : 0.f;
        }
        float l[4][8];
#pragma unroll
        for (int i=0;i<4;i++)
#pragma unroll
            for (int j=0;j<8;j++) l[i][j]=0.f;
#pragma unroll 5
        for (int d=0; d<HDIM; d++){
            float kv[8];
#pragma unroll
            for (int j=0;j<8;j++) kv[j] = kT[d*KSTR + lane + 32*j];
#pragma unroll
            for (int i=0;i<4;i++){
                float qv = (d<32)? __shfl_sync(0xffffffffu, qd[i], d)
                                 : __shfl_sync(0xffffffffu, qd2[i], d-32);
#pragma unroll
                for (int j=0;j<8;j++) l[i][j] += qv*kv[j];
            }
        }
        if (iswin){
#pragma unroll
            for (int i=0;i<4;i++){
                const float* brow = g_biasf + head*65536 + (qi0+i)*256;
                const float* mrow = mask + (size_t)grp*65536 + (qi0+i)*256;
                float mx = -1e30f;
#pragma unroll
                for (int j=0;j<8;j++){
                    l[i][j] = l[i][j]*rs + brow[lane+32*j] + mrow[lane+32*j];
                    mx = fmaxf(mx, l[i][j]);
                }
#pragma unroll
                for (int o=16;o;o>>=1) mx = fmaxf(mx, __shfl_xor_sync(0xffffffffu, mx, o));
                float sum = 0.f;
#pragma unroll
                for (int j=0;j<8;j++){ l[i][j] = expf(l[i][j]-mx); sum += l[i][j]; }
#pragma unroll
                for (int o=16;o;o>>=1) sum += __shfl_xor_sync(0xffffffffu, sum, o);
                float inv = 1.0f/sum;
#pragma unroll
                for (int j=0;j<8;j++) ps[(wid*4+i)*256 + lane + 32*j] = l[i][j]*inv;
            }
        } else {
#pragma unroll
            for (int i=0;i<4;i++){
                float mx = -1e30f;
#pragma unroll
                for (int j=0;j<8;j++){ l[i][j] *= rs; mx = fmaxf(mx, l[i][j]); }
#pragma unroll
                for (int o=16;o;o>>=1) mx = fmaxf(mx, __shfl_xor_sync(0xffffffffu, mx, o));
                float sum = 0.f;
#pragma unroll
                for (int j=0;j<8;j++){ l[i][j] = expf(l[i][j]-mx); sum += l[i][j]; }
#pragma unroll
                for (int o=16;o;o>>=1) sum += __shfl_xor_sync(0xffffffffu, sum, o);
                float inv = 1.0f/sum;
#pragma unroll
                for (int j=0;j<8;j++) ps[(wid*4+i)*256 + lane + 32*j] = l[i][j]*inv;
            }
        }
        __syncwarp();
        float a0[4]={0,0,0,0}, a1[4]={0,0,0,0};
        int d2ok = (lane<3);
#pragma unroll 2
        for (int m=0;m<256;m+=4){
            float4 vv  = *(const float4*)&vT[lane*KSTR+m];
            float4 vv2 = d2ok ? *(const float4*)&vT[(lane+32)*KSTR+m]
                              : make_float4(0.f,0.f,0.f,0.f);
#pragma unroll
            for (int i=0;i<4;i++){
                float4 pm = *(const float4*)&ps[(wid*4+i)*256+m];
                a0[i] += pm.x*vv.x + pm.y*vv.y + pm.z*vv.z + pm.w*vv.w;
                a1[i] += pm.x*vv2.x + pm.y*vv2.y + pm.z*vv2.z + pm.w*vv2.w;
            }
        }
        float* obase = iswin ? g_win : g_aca;
#pragma unroll
        for (int i=0;i<4;i++){
            float* orow = obase + ((size_t)b*NTOK + tq[i])*CDIM + head*HDIM;
            orow[lane] = a0[i];
            if (lane<3) orow[lane+32] = a1[i];
        }
        __syncwarp();
    }
}

// ---------- gather td features into hcat[:,420:516] ----------
__global__ void tdgather_kernel()
{
    int i = blockIdx.x*256 + threadIdx.x;
    int row = i/96, j = i - row*96;
    int b = row >> 14;
    int tk = g_tkid[row];
    g_hcat[(size_t)row*HF2C + MLPH + j] = g_ftd[((b<<7)+tk)*DTD + j];
}

// ---------- depthwise 5x5 conv + gelu + residual (register sliding window) ----------
__global__ __launch_bounds__(256) void conv_kernel(const float* __restrict__ dw_w,
                                                   const float* __restrict__ dw_b)
{
    __shared__ float s[144*32];
    __shared__ float wsm[32*25];
    int c0 = blockIdx.x*32;
    int tile = blockIdx.y;
    int ty0=(tile>>4)*8, tx0=(tile&15)*8;
    int b = blockIdx.z;
    int cx = threadIdx.x, py = threadIdx.y;
    int tid = py*32+cx;
    for (int f=tid; f<144*32; f+=256){
        int p=f>>5, ch=f&31;
        int gy=ty0-2+p/12, gx=tx0-2+p%12;
        int c=c0+ch;
        float v=0.f;
        if (gy>=0&&gy<128&&gx>=0&&gx<128&&c<HF2C)
            v = g_hcat[((size_t)(b*NTOK+gy*128+gx))*HF2C + c];
        s[f]=v;
    }
    for (int f=tid; f<32*25; f+=256){
        int ch=f/25, k=f-ch*25; int c=c0+ch;
        wsm[f] = (c<HF2C)? dw_w[c*25+k] : 0.f;
    }
    __syncthreads();
    int c = c0+cx;
    if (c>=HF2C) return;
    float bsv = dw_b[c];
    float wr[25];
#pragma unroll
    for (int k=0;k<25;k++) wr[k]=wsm[cx*25+k];
    float acc[8];
#pragma unroll
    for (int px=0;px<8;px++) acc[px]=0.f;
    float center[8];
#pragma unroll
    for (int ky=0;ky<5;ky++){
        float r[12];
#pragma unroll
        for (int xx=0;xx<12;xx++) r[xx] = s[((py+ky)*12+xx)*32+cx];
        if (ky==2){
#pragma unroll
            for (int px=0;px<8;px++) center[px] = r[px+2];
        }
#pragma unroll
        for (int px=0;px<8;px++){
#pragma unroll
            for (int kx=0;kx<5;kx++)
                acc[px] += wr[ky*5+kx]*r[px+kx];
        }
    }
#pragma unroll
    for (int px=0;px<8;px++){
        float o = center[px] + gelu_exact(acc[px]+bsv);
        g_hcat2[((size_t)(b*NTOK+(ty0+py)*128+(tx0+px)))*HF2C + c] = o;
    }
}

#define ATD_SMEM ((MTOK*CDIM + DRED*MTOK + 8*4*MTOK)*4)

static int find_nth(const int* s, int n, int sz, int nth){
    int c=0;
    for (int i=0;i<n;i++){ if (s[i]==sz){ if (c==nth) return i; c++; } }
    return 0;
}

extern "C" void kernel_launch(void* const* d_in, const int* in_sizes, int n_in,
                              void* d_out, int out_size)
{
    const float *x,*td,*attn_mask,*g1,*b1,*g2,*b2,*wqkv_w,*wqkv_b,*wq_w,*wq_b;
    const float *wk_w,*wk_b,*wv_w,*wv_b,*atd_scale,*aca_w,*aca_b,*rpb,*winp_w,*winp_b;
    const float *fctd_w,*fctd_b,*fc1_w,*fc1_b,*dw_w,*dw_b,*fc2_w,*fc2_b;
    const int *rpi;

    if (in_sizes[0] == 13762560){
        bool sig = (in_sizes[2] > 1000000);
        x         = (const float*)d_in[0];
        td        = (const float*)d_in[1];
        attn_mask = (const float*)(sig ? d_in[2] : d_in[29]);
        int k = sig ? 3 : 2;
        g1 = (const float*)d_in[k+0];   b1 = (const float*)d_in[k+1];
        g2 = (const float*)d_in[k+2];   b2 = (const float*)d_in[k+3];
        wqkv_w = (const float*)d_in[k+4]; wqkv_b = (const float*)d_in[k+5];
        wq_w = (const float*)d_in[k+6];  wq_b = (const float*)d_in[k+7];
        wk_w = (const float*)d_in[k+8];  wk_b = (const float*)d_in[k+9];
        wv_w = (const float*)d_in[k+10]; wv_b = (const float*)d_in[k+11];
        atd_scale = (const float*)d_in[k+12];
        aca_w = (const float*)d_in[k+13]; aca_b = (const float*)d_in[k+14];
        rpb = (const float*)d_in[k+15];
        winp_w = (const float*)d_in[k+16]; winp_b = (const float*)d_in[k+17];
        fctd_w = (const float*)d_in[k+18]; fctd_b = (const float*)d_in[k+19];
        fc1_w = (const float*)d_in[k+20]; fc1_b = (const float*)d_in[k+21];
        dw_w = (const float*)d_in[k+22];  dw_b = (const float*)d_in[k+23];
        fc2_w = (const float*)d_in[k+24]; fc2_b = (const float*)d_in[k+25];
        rpi = (const int*)d_in[k+26];
    } else {
        x         = (const float*)d_in[find_nth(in_sizes,n_in,13762560,0)];
        td        = (const float*)d_in[find_nth(in_sizes,n_in,107520,0)];
        attn_mask = (const float*)d_in[find_nth(in_sizes,n_in,4194304,0)];
        wqkv_w    = (const float*)d_in[find_nth(in_sizes,n_in,132300,0)];
        wqkv_b    = (const float*)d_in[find_nth(in_sizes,n_in,630,0)];
        fc2_w     = (const float*)d_in[find_nth(in_sizes,n_in,108360,0)];
        fc1_w     = (const float*)d_in[find_nth(in_sizes,n_in,88200,0)];
        fc1_b     = (const float*)d_in[find_nth(in_sizes,n_in,420,0)];
        fctd_w    = (const float*)d_in[find_nth(in_sizes,n_in,20160,0)];
        fctd_b    = (const float*)d_in[find_nth(in_sizes,n_in,96,0)];
        dw_w      = (const float*)d_in[find_nth(in_sizes,n_in,12900,0)];
        dw_b      = (const float*)d_in[find_nth(in_sizes,n_in,516,0)];
        rpb       = (const float*)d_in[find_nth(in_sizes,n_in,5766,0)];
        rpi       = (const int*)  d_in[find_nth(in_sizes,n_in,65536,0)];
        aca_w  = (const float*)d_in[find_nth(in_sizes,n_in,44100,0)];
        winp_w = (const float*)d_in[find_nth(in_sizes,n_in,44100,1)];
        wv_w   = (const float*)d_in[find_nth(in_sizes,n_in,44100,2)];
        wk_w = (const float*)d_in[find_nth(in_sizes,n_in,4200,0)];
        wq_w = (const float*)d_in[find_nth(in_sizes,n_in,4200,1)];
        wk_b = (const float*)d_in[find_nth(in_sizes,n_in,20,0)];
        wq_b = (const float*)d_in[find_nth(in_sizes,n_in,20,1)];
        aca_b  = (const float*)d_in[find_nth(in_sizes,n_in,210,0)];
        b1     = (const float*)d_in[find_nth(in_sizes,n_in,210,1)];
        b2     = (const float*)d_in[find_nth(in_sizes,n_in,210,2)];
        fc2_b  = (const float*)d_in[find_nth(in_sizes,n_in,210,3)];
        g1     = (const float*)d_in[find_nth(in_sizes,n_in,210,4)];
        g2     = (const float*)d_in[find_nth(in_sizes,n_in,210,5)];
        winp_b = (const float*)d_in[find_nth(in_sizes,n_in,210,6)];
        wv_b   = (const float*)d_in[find_nth(in_sizes,n_in,210,7)];
        atd_scale = (const float*)d_in[find_nth(in_sizes,n_in,1,0)];
    }

    float *p_xn, *p_qkv, *p_x2, *p_xn2, *p_aca, *p_win, *p_hcat, *p_hcat2;
    cudaGetSymbolAddress((void**)&p_xn,    g_xn);
    cudaGetSymbolAddress((void**)&p_qkv,   g_qkv);
    cudaGetSymbolAddress((void**)&p_x2,    g_x2);
    cudaGetSymbolAddress((void**)&p_xn2,   g_xn2);
    cudaGetSymbolAddress((void**)&p_aca,   g_aca);
    cudaGetSymbolAddress((void**)&p_win,   g_win);
    cudaGetSymbolAddress((void**)&p_hcat,  g_hcat);
    cudaGetSymbolAddress((void**)&p_hcat2, g_hcat2);

    cudaFuncSetAttribute(atd_kernel,  cudaFuncAttributeMaxDynamicSharedMemorySize, ATD_SMEM);
    cudaFuncSetAttribute(attn_kernel, cudaFuncAttributeMaxDynamicSharedMemorySize, ATT_SMEM);

    cudaStream_t s1;
    cudaStreamCreateWithFlags(&s1, cudaStreamNonBlocking);
    cudaEvent_t e0, eLN, eSort, eTd;
    cudaEventCreateWithFlags(&e0,   cudaEventDisableTiming);
    cudaEventCreateWithFlags(&eLN,  cudaEventDisableTiming);
    cudaEventCreateWithFlags(&eSort,cudaEventDisableTiming);
    cudaEventCreateWithFlags(&eTd,  cudaEventDisableTiming);

    // fork s1 from the (captured) legacy stream
    cudaEventRecord(e0, 0);
    cudaStreamWaitEvent(s1, e0, 0);

    // s1: independent prep
    biasprep_kernel<<<256,256,0,s1>>>(rpb, rpi);
    kv_kernel<<<BATCH*MTOK,256,0,s1>>>(td, wk_w,wk_b, wv_w,wv_b, fctd_w,fctd_b);

    // s0: layernorm; then big qkv GEMM
    ln_kernel<<<ROWS/8,256>>>(x, g1, b1, p_xn, ROWS);
    cudaEventRecord(eLN, 0);
    cudaStreamWaitEvent(s1, eLN, 0);
    sgemm_kernel<<<dim3(5,512),256>>>(p_xn,CDIM, wqkv_w,C3, wqkv_b, nullptr,0,
                                      p_qkv,C3, ROWS,C3,CDIM, 0);

    // s1: ATD chain fully concurrent with qkv GEMM
    qproj_kernel<<<ROWS/4,128,0,s1>>>(wq_w, wq_b);
    atd_kernel<<<BATCH*256,256,ATD_SMEM,s1>>>(x, atd_scale);
    sort_kernel<<<BATCH,64,0,s1>>>();
    cudaEventRecord(eSort, s1);
    tdgather_kernel<<<ROWS*96/256,256,0,s1>>>();
    cudaEventRecord(eTd, s1);

    // s0: combined attention (needs qkv done [s0 order] + sort)
    cudaStreamWaitEvent(0, eSort, 0);
    attn_kernel<<<dim3(12,64,BATCH),256,ATT_SMEM>>>(attn_mask);

    // fused dual projection: x2 += aca@Wa + win@Ww + ba + bw
    sgemm_dual<<<dim3(2,512),256>>>(p_aca, p_win, aca_w, winp_w, aca_b, winp_b, p_x2);

    ln_kernel<<<ROWS/8,256>>>(p_x2, g2, b2, p_xn2, ROWS);
    sgemm_kernel<<<dim3(4,512),256>>>(p_xn2,CDIM, fc1_w,MLPH, fc1_b, nullptr,0,
                                      p_hcat,HF2C, ROWS,MLPH,CDIM, 1);
    cudaStreamWaitEvent(0, eTd, 0);
    conv_kernel<<<dim3(17,256,BATCH),dim3(32,8)>>>(dw_w, dw_b);
    sgemm_kernel<<<dim3(2,512),256>>>(p_hcat2,HF2C, fc2_w,CDIM, fc2_b, p_x2,CDIM,
                                      (float*)d_out,CDIM, ROWS,CDIM,HF2C, 0);
}

// round 17
// speedup vs baseline: 1.0965x; 1.0173x over previous
#include <cuda_runtime.h>
#include <math.h>

#define BATCH 4
#define NTOK 16384
#define CDIM 210
#define C3   630
#define HDIM 35
#define MTOK 128
#define DRED 20
#define DTD 96
#define MLPH 420
#define HF2C 516
#define ROWS (BATCH*NTOK)
#define LOGM 4.852030263919617f

__device__ float g_xn  [ROWS*CDIM];
__device__ float g_qkv [(size_t)ROWS*C3];
__device__ float g_x2  [ROWS*CDIM];
__device__ float g_xn2 [ROWS*CDIM];
__device__ float g_q   [ROWS*DRED];
__device__ float g_kn  [BATCH*MTOK*DRED];
__device__ float g_v   [BATCH*MTOK*CDIM];
__device__ float g_ftd [BATCH*MTOK*DTD];
__device__ int   g_tkid[ROWS];
__device__ int   g_sidx[ROWS];
__device__ float g_aca [ROWS*CDIM];
__device__ float g_win [ROWS*CDIM];
__device__ float g_biasf[6*65536];
__device__ float g_hcat [(size_t)ROWS*HF2C];
__device__ float g_hcat2[(size_t)ROWS*HF2C];

__device__ __forceinline__ float gelu_exact(float v){
    return 0.5f*v*(1.0f+erff(v*0.7071067811865476f));
}

// ---------- LayerNorm: warp per row ----------
__global__ void ln_kernel(const float* __restrict__ in, const float* __restrict__ gam,
                          const float* __restrict__ bet, float* __restrict__ out, int rows)
{
    int warp = (blockIdx.x*blockDim.x + threadIdx.x) >> 5;
    int lane = threadIdx.x & 31;
    if (warp >= rows) return;
    const float* r = in + (size_t)warp*CDIM;
    float v[7]; float s = 0.f;
#pragma unroll
    for (int j=0;j<7;j++){ int k = lane + 32*j; v[j] = (k<CDIM)? r[k] : 0.f; s += v[j]; }
#pragma unroll
    for (int o=16;o;o>>=1) s += __shfl_xor_sync(0xffffffffu, s, o);
    float mu = s * (1.0f/CDIM);
    float vs = 0.f;
#pragma unroll
    for (int j=0;j<7;j++){ int k = lane + 32*j; if (k<CDIM){ float d = v[j]-mu; vs += d*d; } }
#pragma unroll
    for (int o=16;o;o>>=1) vs += __shfl_xor_sync(0xffffffffu, vs, o);
    float rstd = rsqrtf(vs*(1.0f/CDIM) + 1e-5f);
    float* o2 = out + (size_t)warp*CDIM;
#pragma unroll
    for (int j=0;j<7;j++){ int k = lane + 32*j; if (k<CDIM) o2[k] = (v[j]-mu)*rstd*gam[k] + bet[k]; }
}

// ---------- SGEMM: double-buffered 128x128x8, 8x8/thread ----------
__global__ __launch_bounds__(256,2) void sgemm_kernel(
        const float* __restrict__ A, int lda,
        const float* __restrict__ W, int ldw,
        const float* __restrict__ bias,
        const float* __restrict__ addp, int ldadd,
        float* __restrict__ C, int ldc,
        int Mr, int Nc, int K, int act)
{
    __shared__ float As[2][8][128];
    __shared__ float Bs[2][8][128];
    int tid = threadIdx.x;
    int tx = tid & 15, ty = tid >> 4;
    int row0 = blockIdx.y * 128, col0 = blockIdx.x * 128;
    float acc[8][8];
#pragma unroll
    for (int i=0;i<8;i++)
#pragma unroll
        for (int j=0;j<8;j++) acc[i][j]=0.f;
    int nk = (K+7)/8;
    float ra[4], rb[4];
    {
#pragma unroll
        for (int i=0;i<4;i++){
            int f = tid + i*256;
            int r = f>>3, kk = f&7;
            int gr = row0+r;
            ra[i] = (gr<Mr && kk<K)? A[(size_t)gr*lda + kk] : 0.f;
            int kb = f>>7, cb = f&127;
            int gc = col0+cb;
            rb[i] = (kb<K && gc<Nc)? W[(size_t)kb*ldw + gc] : 0.f;
        }
#pragma unroll
        for (int i=0;i<4;i++){
            int f = tid + i*256;
            As[0][f&7][f>>3] = ra[i];
            Bs[0][f>>7][f&127] = rb[i];
        }
    }
    __syncthreads();
    for (int kt=0; kt<nk; kt++){
        int cur = kt&1;
        if (kt+1 < nk){
            int k0 = (kt+1)*8;
#pragma unroll
            for (int i=0;i<4;i++){
                int f = tid + i*256;
                int r = f>>3, kk = f&7;
                int gr = row0+r, gk = k0+kk;
                ra[i] = (gr<Mr && gk<K)? A[(size_t)gr*lda + gk] : 0.f;
                int kb = f>>7, cb = f&127;
                int gc = col0+cb, gkb = k0+kb;
                rb[i] = (gkb<K && gc<Nc)? W[(size_t)gkb*ldw + gc] : 0.f;
            }
        }
#pragma unroll
        for (int kk=0;kk<8;kk++){
            float4 a0 = *(const float4*)&As[cur][kk][ty*8];
            float4 a1 = *(const float4*)&As[cur][kk][ty*8+4];
            float4 b0 = *(const float4*)&Bs[cur][kk][tx*8];
            float4 b1 = *(const float4*)&Bs[cur][kk][tx*8+4];
            float av[8] = {a0.x,a0.y,a0.z,a0.w,a1.x,a1.y,a1.z,a1.w};
            float bv[8] = {b0.x,b0.y,b0.z,b0.w,b1.x,b1.y,b1.z,b1.w};
#pragma unroll
            for (int i=0;i<8;i++)
#pragma unroll
                for (int j=0;j<8;j++) acc[i][j] += av[i]*bv[j];
        }
        if (kt+1 < nk){
            int nxt = cur^1;
#pragma unroll
            for (int i=0;i<4;i++){
                int f = tid + i*256;
                As[nxt][f&7][f>>3] = ra[i];
                Bs[nxt][f>>7][f&127] = rb[i];
            }
            __syncthreads();
        }
    }
    if (row0+128<=Mr && col0+128<=Nc && act==0 && !addp && ((ldc&1)==0)){
#pragma unroll
        for (int i=0;i<8;i++){
            int r = row0 + ty*8 + i;
            float* cp = C + (size_t)r*ldc + col0 + tx*8;
#pragma unroll
            for (int j=0;j<4;j++){
                int c = col0 + tx*8 + 2*j;
                float2 v2 = make_float2(acc[i][2*j] + bias[c], acc[i][2*j+1] + bias[c+1]);
                *(float2*)(cp + 2*j) = v2;
            }
        }
        return;
    }
#pragma unroll
    for (int i=0;i<8;i++){
        int r = row0 + ty*8 + i;
        if (r >= Mr) continue;
#pragma unroll
        for (int j=0;j<8;j++){
            int c = col0 + tx*8 + j;
            if (c >= Nc) continue;
            float v = acc[i][j] + bias[c];
            if (act==1) v = gelu_exact(v);
            if (addp) v += addp[(size_t)r*ldadd + c];
            C[(size_t)r*ldc + c] = v;
        }
    }
}

// ---------- fused dual-projection GEMM: C += A1@W1 + A2@W2 + b1 + b2 ----------
__global__ __launch_bounds__(256,2) void sgemm_dual(
        const float* __restrict__ A1, const float* __restrict__ A2,
        const float* __restrict__ W1, const float* __restrict__ W2,
        const float* __restrict__ b1v, const float* __restrict__ b2v,
        float* __restrict__ C)
{
    __shared__ float As[2][8][128];
    __shared__ float Bs[2][8][128];
    int tid = threadIdx.x;
    int tx = tid & 15, ty = tid >> 4;
    int row0 = blockIdx.y * 128, col0 = blockIdx.x * 128;
    float acc[8][8];
#pragma unroll
    for (int i=0;i<8;i++)
#pragma unroll
        for (int j=0;j<8;j++) acc[i][j]=0.f;
    const int K = 420, Nc = 210;
    int nk = (K+7)/8;
    float ra[4], rb[4];
    {
#pragma unroll
        for (int i=0;i<4;i++){
            int f = tid + i*256;
            int r = row0 + (f>>3), kk = f&7;
            ra[i] = A1[(size_t)r*210 + kk];
            int kb = f>>7, cb = f&127;
            int gc = col0+cb;
            rb[i] = (gc<Nc)? W1[kb*210 + gc] : 0.f;
        }
#pragma unroll
        for (int i=0;i<4;i++){
            int f = tid + i*256;
            As[0][f&7][f>>3] = ra[i];
            Bs[0][f>>7][f&127] = rb[i];
        }
    }
    __syncthreads();
    for (int kt=0; kt<nk; kt++){
        int cur = kt&1;
        if (kt+1 < nk){
            int k0 = (kt+1)*8;
#pragma unroll
            for (int i=0;i<4;i++){
                int f = tid + i*256;
                int r = row0 + (f>>3), gk = k0 + (f&7);
                float a = 0.f;
                if (gk < 210)       a = A1[(size_t)r*210 + gk];
                else if (gk < 420)  a = A2[(size_t)r*210 + gk-210];
                ra[i] = a;
                int gkb = k0 + (f>>7), cb = f&127;
                int gc = col0+cb;
                float b = 0.f;
                if (gc < Nc){
                    if (gkb < 210)      b = W1[gkb*210 + gc];
                    else if (gkb < 420) b = W2[(gkb-210)*210 + gc];
                }
                rb[i] = b;
            }
        }
#pragma unroll
        for (int kk=0;kk<8;kk++){
            float4 a0 = *(const float4*)&As[cur][kk][ty*8];
            float4 a1 = *(const float4*)&As[cur][kk][ty*8+4];
            float4 b0 = *(const float4*)&Bs[cur][kk][tx*8];
            float4 b1 = *(const float4*)&Bs[cur][kk][tx*8+4];
            float av[8] = {a0.x,a0.y,a0.z,a0.w,a1.x,a1.y,a1.z,a1.w};
            float bv[8] = {b0.x,b0.y,b0.z,b0.w,b1.x,b1.y,b1.z,b1.w};
#pragma unroll
            for (int i=0;i<8;i++)
#pragma unroll
                for (int j=0;j<8;j++) acc[i][j] += av[i]*bv[j];
        }
        if (kt+1 < nk){
            int nxt = cur^1;
#pragma unroll
            for (int i=0;i<4;i++){
                int f = tid + i*256;
                As[nxt][f&7][f>>3] = ra[i];
                Bs[nxt][f>>7][f&127] = rb[i];
            }
            __syncthreads();
        }
    }
#pragma unroll
    for (int i=0;i<8;i++){
        int r = row0 + ty*8 + i;
#pragma unroll
        for (int j=0;j<8;j++){
            int c = col0 + tx*8 + j;
            if (c >= Nc) continue;
            size_t idx = (size_t)r*210 + c;
            C[idx] = C[idx] + acc[i][j] + b1v[c] + b2v[c];
        }
    }
}

// ---------- q projection + l2norm: warp per row ----------
__global__ void qproj_kernel(const float* __restrict__ wq, const float* __restrict__ bq)
{
    __shared__ float s[4][CDIM];
    int w = threadIdx.x>>5, lane = threadIdx.x&31;
    int row = blockIdx.x*4 + w;
    const float* r = g_xn + (size_t)row*CDIM;
    for (int k=lane;k<CDIM;k+=32) s[w][k] = r[k];
    __syncwarp();
    float acc = 0.f;
    if (lane < DRED){
        acc = bq[lane];
        for (int k=0;k<CDIM;k++) acc += s[w][k]*wq[k*DRED+lane];
    }
    float sq = (lane<DRED)? acc*acc : 0.f;
#pragma unroll
    for (int o=16;o;o>>=1) sq += __shfl_xor_sync(0xffffffffu, sq, o);
    float den = fmaxf(sqrtf(sq), 1e-12f);
    if (lane < DRED) g_q[(size_t)row*DRED + lane] = acc/den;
}

// ---------- td projections ----------
__global__ void kv_kernel(const float* __restrict__ td,
                          const float* __restrict__ wk_w, const float* __restrict__ wk_b,
                          const float* __restrict__ wv_w, const float* __restrict__ wv_b,
                          const float* __restrict__ ftd_w, const float* __restrict__ ftd_b)
{
    __shared__ float tr[CDIM];
    __shared__ float ks_s[DRED];
    __shared__ float nrm_s;
    int rm = blockIdx.x;
    int b = rm >> 7, m = rm & 127;
    int t = threadIdx.x;
    const float* trow = td + (size_t)rm*CDIM;
    if (t < CDIM) tr[t] = trow[t];
    __syncthreads();
    if (t < CDIM){
        float a = wv_b[t];
        for (int k=0;k<CDIM;k++) a += tr[k]*wv_w[k*CDIM+t];
        g_v[(size_t)rm*CDIM + t] = a;
    }
    if (t < DTD){
        float a = ftd_b[t];
        for (int k=0;k<CDIM;k++) a += tr[k]*ftd_w[k*DTD+t];
        g_ftd[(size_t)rm*DTD + t] = a;
    }
    if (t < DRED){
        float a = wk_b[t];
        for (int k=0;k<CDIM;k++) a += tr[k]*wk_w[k*DRED+t];
        ks_s[t] = a;
    }
    __syncthreads();
    if (t==0){
        float s=0.f;
        for (int j=0;j<DRED;j++) s += ks_s[j]*ks_s[j];
        nrm_s = fmaxf(sqrtf(s), 1e-12f);
    }
    __syncthreads();
    if (t < DRED) g_kn[b*(MTOK*DRED) + t*MTOK + m] = ks_s[t]/nrm_s;
}

// ---------- fused ATD cross-attn (4 tokens/warp-iter) ----------
__global__ void atd_kernel(const float* __restrict__ x, const float* __restrict__ atd_scale)
{
    extern __shared__ float sm2[];
    float* vs  = sm2;
    float* knT = vs + MTOK*CDIM;
    float* pbuf= knT + DRED*MTOK;
    int tid = threadIdx.x, wid = tid>>5, lane = tid&31;
    int b  = blockIdx.x >> 8;
    int n0 = (blockIdx.x & 255) * 64;
    for (int f=tid; f<MTOK*CDIM; f+=256) vs[f]  = g_v [b*(MTOK*CDIM)+f];
    for (int f=tid; f<DRED*MTOK; f+=256) knT[f] = g_kn[b*(MTOK*DRED)+f];
    float sc = atd_scale[0];
    sc = 1.0f + fminf(fmaxf(sc,0.0f),3.0f)*LOGM;
    __syncthreads();
    for (int g=0; g<2; g++){
        int n = n0 + wid*8 + g*4;
        size_t rbase = (size_t)b*NTOK + n;
        float ql[4];
#pragma unroll
        for (int i=0;i<4;i++)
            ql[i] = (lane<DRED)? g_q[(rbase+i)*DRED + lane] : 0.f;
        float lg[4][4];
#pragma unroll
        for (int i=0;i<4;i++)
#pragma unroll
            for (int mm=0;mm<4;mm++) lg[i][mm]=0.f;
        for (int j=0;j<DRED;j++){
            float kv[4];
#pragma unroll
            for (int mm=0;mm<4;mm++) kv[mm] = knT[j*MTOK + lane + 32*mm];
#pragma unroll
            for (int i=0;i<4;i++){
                float qv = __shfl_sync(0xffffffffu, ql[i], j);
#pragma unroll
                for (int mm=0;mm<4;mm++) lg[i][mm] += qv*kv[mm];
            }
        }
#pragma unroll
        for (int i=0;i<4;i++){
#pragma unroll
            for (int mm=0;mm<4;mm++) lg[i][mm] *= sc;
            float bv = lg[i][0]; int bi = lane;
#pragma unroll
            for (int mm=1;mm<4;mm++){
                int m = lane+32*mm;
                if (lg[i][mm] > bv){ bv = lg[i][mm]; bi = m; }
            }
#pragma unroll
            for (int o=16;o;o>>=1){
                float ov = __shfl_xor_sync(0xffffffffu, bv, o);
                int   oi = __shfl_xor_sync(0xffffffffu, bi, o);
                if (ov > bv || (ov==bv && oi<bi)){ bv = ov; bi = oi; }
            }
            float sum = 0.f;
#pragma unroll
            for (int mm=0;mm<4;mm++){ lg[i][mm] = expf(lg[i][mm]-bv); sum += lg[i][mm]; }
#pragma unroll
            for (int o=16;o;o>>=1) sum += __shfl_xor_sync(0xffffffffu, sum, o);
            float inv = 1.0f/sum;
#pragma unroll
            for (int mm=0;mm<4;mm++) pbuf[(wid*4+i)*MTOK + lane + 32*mm] = lg[i][mm]*inv;
            if (lane==0) g_tkid[rbase+i] = bi;
        }
        __syncwarp();
        float a[4][7];
#pragma unroll
        for (int i=0;i<4;i++)
#pragma unroll
            for (int k=0;k<7;k++) a[i][k]=0.f;
#pragma unroll 2
        for (int m=0;m<MTOK;m++){
            float vv[7];
            const float* vrow = vs + m*CDIM;
#pragma unroll
            for (int k=0;k<6;k++) vv[k] = vrow[lane+32*k];
            vv[6] = (lane<18)? vrow[lane+192] : 0.f;
#pragma unroll
            for (int i=0;i<4;i++){
                float pm = pbuf[(wid*4+i)*MTOK + m];
#pragma unroll
                for (int k=0;k<7;k++) a[i][k] += pm*vv[k];
            }
        }
#pragma unroll
        for (int i=0;i<4;i++){
            const float* xr = x + (rbase+i)*CDIM;
            float* orow = g_x2 + (rbase+i)*CDIM;
#pragma unroll
            for (int k=0;k<6;k++) orow[lane+32*k] = xr[lane+32*k] + a[i][k];
            if (lane<18) orow[lane+192] = xr[lane+192] + a[i][6];
        }
        __syncwarp();
    }
}

// ---------- stable counting sort per batch ----------
__global__ void sort_kernel()
{
    __shared__ int cnt[64*128];
    __shared__ int binbase[128];
    int b = blockIdx.x, t = threadIdx.x;
    const int* key = g_tkid + b*NTOK;
    int* out = g_sidx + b*NTOK;
    for (int i=t;i<64*128;i+=64) cnt[i]=0;
    __syncthreads();
    for (int i=0;i<256;i++){ int k = key[t*256+i]; cnt[t*128+k]++; }
    __syncthreads();
    for (int bb=t; bb<128; bb+=64){
        int tot=0;
        for (int th=0; th<64; th++){ int v = cnt[th*128+bb]; cnt[th*128+bb]=tot; tot+=v; }
        binbase[bb]=tot;
    }
    __syncthreads();
    if (t==0){ int s=0; for (int bn=0;bn<128;bn++){ int v=binbase[bn]; binbase[bn]=s; s+=v; } }
    __syncthreads();
    for (int i=0;i<256;i++){
        int tok = t*256+i;
        int k = key[tok];
        int pos = binbase[k] + cnt[t*128+k]++;
        out[pos] = tok;
    }
}

// ---------- window bias precompute ----------
__global__ void biasprep_kernel(const float* __restrict__ rpb, const int* __restrict__ rpi)
{
    int i = blockIdx.x*256 + threadIdx.x;
    int r = rpi[i];
#pragma unroll
    for (int h=0;h<6;h++) g_biasf[h*65536 + i] = rpb[r*6 + h];
}

// ---------- combined attention (grouped + window), per-batch launch ----------
#define KSTR 260
#define ATT_SMEM ((2*35*KSTR + 8*4*256 + 256)*4)

__global__ __launch_bounds__(256,2) void attn_kernel(const float* __restrict__ mask, int b)
{
    extern __shared__ float sm[];
    float* kT = sm;
    float* vT = sm + 35*KSTR;
    float* ps = sm + 2*35*KSTR;
    int*  tok = (int*)(sm + 2*35*KSTR + 8*4*256);
    int hsel = blockIdx.x;
    int iswin = (hsel >= 6);
    int head = iswin ? (hsel-6) : hsel;
    int grp = blockIdx.y;
    int tid = threadIdx.x, wid = tid>>5, lane = tid&31;
    if (iswin){
        int wh = grp>>3, ww = grp&7;
        int y  = ((wh<<4) + (tid>>4) + 8) & 127;
        int xq = ((ww<<4) + (tid&15) + 8) & 127;
        tok[tid] = y*128 + xq;
    } else {
        tok[tid] = g_sidx[b*NTOK + grp*256 + tid];
    }
    __syncthreads();
    const float* qb = g_qkv + (size_t)b*NTOK*C3;
    for (int i=wid; i<256; i+=8){
        const float* p = qb + (size_t)tok[i]*C3 + head*HDIM;
        kT[lane*KSTR+i] = p[CDIM + lane];
        vT[lane*KSTR+i] = p[2*CDIM + lane];
        if (lane<3){
            kT[(lane+32)*KSTR+i] = p[CDIM + lane+32];
            vT[(lane+32)*KSTR+i] = p[2*CDIM + lane+32];
        }
    }
    __syncthreads();
    const float rs = 0.16903085094570331f;
    for (int it=0; it<8; it++){
        int qi0 = wid*32 + it*4;
        int tq[4]; float qd[4], qd2[4];
#pragma unroll
        for (int i=0;i<4;i++){
            tq[i] = tok[qi0+i];
            const float* qp = qb + (size_t)tq[i]*C3 + head*HDIM;
            qd[i]  = qp[lane];
            qd2[i] = (lane<3)? qp[lane+32] : 0.f;
        }
        float l[4][8];
#pragma unroll
        for (int i=0;i<4;i++)
#pragma unroll
            for (int j=0;j<8;j++) l[i][j]=0.f;
#pragma unroll 5
        for (int d=0; d<HDIM; d++){
            float kv[8];
#pragma unroll
            for (int j=0;j<8;j++) kv[j] = kT[d*KSTR + lane + 32*j];
#pragma unroll
            for (int i=0;i<4;i++){
                float qv = (d<32)? __shfl_sync(0xffffffffu, qd[i], d)
                                 : __shfl_sync(0xffffffffu, qd2[i], d-32);
#pragma unroll
                for (int j=0;j<8;j++) l[i][j] += qv*kv[j];
            }
        }
        if (iswin){
#pragma unroll
            for (int i=0;i<4;i++){
                const float* brow = g_biasf + head*65536 + (qi0+i)*256;
                const float* mrow = mask + (size_t)grp*65536 + (qi0+i)*256;
                float mx = -1e30f;
#pragma unroll
                for (int j=0;j<8;j++){
                    l[i][j] = l[i][j]*rs + brow[lane+32*j] + mrow[lane+32*j];
                    mx = fmaxf(mx, l[i][j]);
                }
#pragma unroll
                for (int o=16;o;o>>=1) mx = fmaxf(mx, __shfl_xor_sync(0xffffffffu, mx, o));
                float sum = 0.f;
#pragma unroll
                for (int j=0;j<8;j++){ l[i][j] = expf(l[i][j]-mx); sum += l[i][j]; }
#pragma unroll
                for (int o=16;o;o>>=1) sum += __shfl_xor_sync(0xffffffffu, sum, o);
                float inv = 1.0f/sum;
#pragma unroll
                for (int j=0;j<8;j++) ps[(wid*4+i)*256 + lane + 32*j] = l[i][j]*inv;
            }
        } else {
#pragma unroll
            for (int i=0;i<4;i++){
                float mx = -1e30f;
#pragma unroll
                for (int j=0;j<8;j++){ l[i][j] *= rs; mx = fmaxf(mx, l[i][j]); }
#pragma unroll
                for (int o=16;o;o>>=1) mx = fmaxf(mx, __shfl_xor_sync(0xffffffffu, mx, o));
                float sum = 0.f;
#pragma unroll
                for (int j=0;j<8;j++){ l[i][j] = expf(l[i][j]-mx); sum += l[i][j]; }
#pragma unroll
                for (int o=16;o;o>>=1) sum += __shfl_xor_sync(0xffffffffu, sum, o);
                float inv = 1.0f/sum;
#pragma unroll
                for (int j=0;j<8;j++) ps[(wid*4+i)*256 + lane + 32*j] = l[i][j]*inv;
            }
        }
        __syncwarp();
        float a0[4]={0,0,0,0}, a1[4]={0,0,0,0};
        int d2ok = (lane<3);
#pragma unroll 2
        for (int m=0;m<256;m+=4){
            float4 vv  = *(const float4*)&vT[lane*KSTR+m];
            float4 vv2 = d2ok ? *(const float4*)&vT[(lane+32)*KSTR+m]
                              : make_float4(0.f,0.f,0.f,0.f);
#pragma unroll
            for (int i=0;i<4;i++){
                float4 pm = *(const float4*)&ps[(wid*4+i)*256+m];
                a0[i] += pm.x*vv.x + pm.y*vv.y + pm.z*vv.z + pm.w*vv.w;
                a1[i] += pm.x*vv2.x + pm.y*vv2.y + pm.z*vv2.z + pm.w*vv2.w;
            }
        }
        float* obase = iswin ? g_win : g_aca;
#pragma unroll
        for (int i=0;i<4;i++){
            float* orow = obase + ((size_t)b*NTOK + tq[i])*CDIM + head*HDIM;
            orow[lane] = a0[i];
            if (lane<3) orow[lane+32] = a1[i];
        }
        __syncwarp();
    }
}

// ---------- gather td features into hcat[:,420:516] (per-batch) ----------
__global__ void tdgather_kernel(int rowbase)
{
    int i = blockIdx.x*256 + threadIdx.x;
    int row = rowbase + i/96, j = i - (i/96)*96;
    int b = row >> 14;
    int tk = g_tkid[row];
    g_hcat[(size_t)row*HF2C + MLPH + j] = g_ftd[((b<<7)+tk)*DTD + j];
}

// ---------- depthwise 5x5 conv + gelu + residual (per-batch) ----------
__global__ __launch_bounds__(256) void conv_kernel(const float* __restrict__ dw_w,
                                                   const float* __restrict__ dw_b, int b)
{
    __shared__ float s[144*32];
    __shared__ float wsm[32*25];
    int c0 = blockIdx.x*32;
    int tile = blockIdx.y;
    int ty0=(tile>>4)*8, tx0=(tile&15)*8;
    int cx = threadIdx.x, py = threadIdx.y;
    int tid = py*32+cx;
    for (int f=tid; f<144*32; f+=256){
        int p=f>>5, ch=f&31;
        int gy=ty0-2+p/12, gx=tx0-2+p%12;
        int c=c0+ch;
        float v=0.f;
        if (gy>=0&&gy<128&&gx>=0&&gx<128&&c<HF2C)
            v = g_hcat[((size_t)(b*NTOK+gy*128+gx))*HF2C + c];
        s[f]=v;
    }
    for (int f=tid; f<32*25; f+=256){
        int ch=f/25, k=f-ch*25; int c=c0+ch;
        wsm[f] = (c<HF2C)? dw_w[c*25+k] : 0.f;
    }
    __syncthreads();
    int c = c0+cx;
    if (c>=HF2C) return;
    float bsv = dw_b[c];
    float wr[25];
#pragma unroll
    for (int k=0;k<25;k++) wr[k]=wsm[cx*25+k];
    float acc[8];
#pragma unroll
    for (int px=0;px<8;px++) acc[px]=0.f;
    float center[8];
#pragma unroll
    for (int ky=0;ky<5;ky++){
        float r[12];
#pragma unroll
        for (int xx=0;xx<12;xx++) r[xx] = s[((py+ky)*12+xx)*32+cx];
        if (ky==2){
#pragma unroll
            for (int px=0;px<8;px++) center[px] = r[px+2];
        }
#pragma unroll
        for (int px=0;px<8;px++){
#pragma unroll
            for (int kx=0;kx<5;kx++)
                acc[px] += wr[ky*5+kx]*r[px+kx];
        }
    }
#pragma unroll
    for (int px=0;px<8;px++){
        float o = center[px] + gelu_exact(acc[px]+bsv);
        g_hcat2[((size_t)(b*NTOK+(ty0+py)*128+(tx0+px)))*HF2C + c] = o;
    }
}

#define ATD_SMEM ((MTOK*CDIM + DRED*MTOK + 8*4*MTOK)*4)

static int find_nth(const int* s, int n, int sz, int nth){
    int c=0;
    for (int i=0;i<n;i++){ if (s[i]==sz){ if (c==nth) return i; c++; } }
    return 0;
}

// streams/events created ONCE (first call = correctness run); the captured
// call performs zero resource allocation -> no device-memory delta in capture.
static cudaStream_t g_s1, g_s2, g_s3;
static cudaEvent_t  g_e0, g_eLN, g_eQKV, g_eSort, g_eC1, g_eC2, g_eC3;
static int g_init = 0;

extern "C" void kernel_launch(void* const* d_in, const int* in_sizes, int n_in,
                              void* d_out, int out_size)
{
    const float *x,*td,*attn_mask,*g1,*b1,*g2,*b2,*wqkv_w,*wqkv_b,*wq_w,*wq_b;
    const float *wk_w,*wk_b,*wv_w,*wv_b,*atd_scale,*aca_w,*aca_b,*rpb,*winp_w,*winp_b;
    const float *fctd_w,*fctd_b,*fc1_w,*fc1_b,*dw_w,*dw_b,*fc2_w,*fc2_b;
    const int *rpi;

    if (in_sizes[0] == 13762560){
        bool sig = (in_sizes[2] > 1000000);
        x         = (const float*)d_in[0];
        td        = (const float*)d_in[1];
        attn_mask = (const float*)(sig ? d_in[2] : d_in[29]);
        int k = sig ? 3 : 2;
        g1 = (const float*)d_in[k+0];   b1 = (const float*)d_in[k+1];
        g2 = (const float*)d_in[k+2];   b2 = (const float*)d_in[k+3];
        wqkv_w = (const float*)d_in[k+4]; wqkv_b = (const float*)d_in[k+5];
        wq_w = (const float*)d_in[k+6];  wq_b = (const float*)d_in[k+7];
        wk_w = (const float*)d_in[k+8];  wk_b = (const float*)d_in[k+9];
        wv_w = (const float*)d_in[k+10]; wv_b = (const float*)d_in[k+11];
        atd_scale = (const float*)d_in[k+12];
        aca_w = (const float*)d_in[k+13]; aca_b = (const float*)d_in[k+14];
        rpb = (const float*)d_in[k+15];
        winp_w = (const float*)d_in[k+16]; winp_b = (const float*)d_in[k+17];
        fctd_w = (const float*)d_in[k+18]; fctd_b = (const float*)d_in[k+19];
        fc1_w = (const float*)d_in[k+20]; fc1_b = (const float*)d_in[k+21];
        dw_w = (const float*)d_in[k+22];  dw_b = (const float*)d_in[k+23];
        fc2_w = (const float*)d_in[k+24]; fc2_b = (const float*)d_in[k+25];
        rpi = (const int*)d_in[k+26];
    } else {
        x         = (const float*)d_in[find_nth(in_sizes,n_in,13762560,0)];
        td        = (const float*)d_in[find_nth(in_sizes,n_in,107520,0)];
        attn_mask = (const float*)d_in[find_nth(in_sizes,n_in,4194304,0)];
        wqkv_w    = (const float*)d_in[find_nth(in_sizes,n_in,132300,0)];
        wqkv_b    = (const float*)d_in[find_nth(in_sizes,n_in,630,0)];
        fc2_w     = (const float*)d_in[find_nth(in_sizes,n_in,108360,0)];
        fc1_w     = (const float*)d_in[find_nth(in_sizes,n_in,88200,0)];
        fc1_b     = (const float*)d_in[find_nth(in_sizes,n_in,420,0)];
        fctd_w    = (const float*)d_in[find_nth(in_sizes,n_in,20160,0)];
        fctd_b    = (const float*)d_in[find_nth(in_sizes,n_in,96,0)];
        dw_w      = (const float*)d_in[find_nth(in_sizes,n_in,12900,0)];
        dw_b      = (const float*)d_in[find_nth(in_sizes,n_in,516,0)];
        rpb       = (const float*)d_in[find_nth(in_sizes,n_in,5766,0)];
        rpi       = (const int*)  d_in[find_nth(in_sizes,n_in,65536,0)];
        aca_w  = (const float*)d_in[find_nth(in_sizes,n_in,44100,0)];
        winp_w = (const float*)d_in[find_nth(in_sizes,n_in,44100,1)];
        wv_w   = (const float*)d_in[find_nth(in_sizes,n_in,44100,2)];
        wk_w = (const float*)d_in[find_nth(in_sizes,n_in,4200,0)];
        wq_w = (const float*)d_in[find_nth(in_sizes,n_in,4200,1)];
        wk_b = (const float*)d_in[find_nth(in_sizes,n_in,20,0)];
        wq_b = (const float*)d_in[find_nth(in_sizes,n_in,20,1)];
        aca_b  = (const float*)d_in[find_nth(in_sizes,n_in,210,0)];
        b1     = (const float*)d_in[find_nth(in_sizes,n_in,210,1)];
        b2     = (const float*)d_in[find_nth(in_sizes,n_in,210,2)];
        fc2_b  = (const float*)d_in[find_nth(in_sizes,n_in,210,3)];
        g1     = (const float*)d_in[find_nth(in_sizes,n_in,210,4)];
        g2     = (const float*)d_in[find_nth(in_sizes,n_in,210,5)];
        winp_b = (const float*)d_in[find_nth(in_sizes,n_in,210,6)];
        wv_b   = (const float*)d_in[find_nth(in_sizes,n_in,210,7)];
        atd_scale = (const float*)d_in[find_nth(in_sizes,n_in,1,0)];
    }

    float *p_xn, *p_qkv, *p_x2, *p_xn2, *p_aca, *p_win, *p_hcat, *p_hcat2;
    cudaGetSymbolAddress((void**)&p_xn,    g_xn);
    cudaGetSymbolAddress((void**)&p_qkv,   g_qkv);
    cudaGetSymbolAddress((void**)&p_x2,    g_x2);
    cudaGetSymbolAddress((void**)&p_xn2,   g_xn2);
    cudaGetSymbolAddress((void**)&p_aca,   g_aca);
    cudaGetSymbolAddress((void**)&p_win,   g_win);
    cudaGetSymbolAddress((void**)&p_hcat,  g_hcat);
    cudaGetSymbolAddress((void**)&p_hcat2, g_hcat2);

    cudaFuncSetAttribute(atd_kernel,  cudaFuncAttributeMaxDynamicSharedMemorySize, ATD_SMEM);
    cudaFuncSetAttribute(attn_kernel, cudaFuncAttributeMaxDynamicSharedMemorySize, ATT_SMEM);

    if (!g_init){
        cudaStreamCreateWithFlags(&g_s1, cudaStreamNonBlocking);
        cudaStreamCreateWithFlags(&g_s2, cudaStreamNonBlocking);
        cudaStreamCreateWithFlags(&g_s3, cudaStreamNonBlocking);
        cudaEventCreateWithFlags(&g_e0,   cudaEventDisableTiming);
        cudaEventCreateWithFlags(&g_eLN,  cudaEventDisableTiming);
        cudaEventCreateWithFlags(&g_eQKV, cudaEventDisableTiming);
        cudaEventCreateWithFlags(&g_eSort,cudaEventDisableTiming);
        cudaEventCreateWithFlags(&g_eC1,  cudaEventDisableTiming);
        cudaEventCreateWithFlags(&g_eC2,  cudaEventDisableTiming);
        cudaEventCreateWithFlags(&g_eC3,  cudaEventDisableTiming);
        g_init = 1;
    }
    cudaStream_t chains[4] = {0, g_s1, g_s2, g_s3};

    // fork s1 from legacy
    cudaEventRecord(g_e0, 0);
    cudaStreamWaitEvent(g_s1, g_e0, 0);

    // s1: prep + ATD chain (independent of qkv GEMM)
    biasprep_kernel<<<256,256,0,g_s1>>>(rpb, rpi);
    kv_kernel<<<BATCH*MTOK,256,0,g_s1>>>(td, wk_w,wk_b, wv_w,wv_b, fctd_w,fctd_b);

    // s0: layernorm; then big qkv GEMM
    ln_kernel<<<ROWS/8,256>>>(x, g1, b1, p_xn, ROWS);
    cudaEventRecord(g_eLN, 0);
    cudaStreamWaitEvent(g_s1, g_eLN, 0);
    sgemm_kernel<<<dim3(5,512),256>>>(p_xn,CDIM, wqkv_w,C3, wqkv_b, nullptr,0,
                                      p_qkv,C3, ROWS,C3,CDIM, 0);
    cudaEventRecord(g_eQKV, 0);

    qproj_kernel<<<ROWS/4,128,0,g_s1>>>(wq_w, wq_b);
    atd_kernel<<<BATCH*256,256,ATD_SMEM,g_s1>>>(x, atd_scale);
    sort_kernel<<<BATCH,64,0,g_s1>>>();
    cudaEventRecord(g_eSort, g_s1);

    // 4 independent per-batch chains
    for (int b=0;b<4;b++){
        cudaStream_t st = chains[b];
        if (b != 0) cudaStreamWaitEvent(st, g_eQKV, 0);
        if (b != 1) cudaStreamWaitEvent(st, g_eSort, 0);
        size_t oC = (size_t)b*NTOK*CDIM;
        size_t oH = (size_t)b*NTOK*HF2C;
        attn_kernel<<<dim3(12,64),256,ATT_SMEM,st>>>(attn_mask, b);
        sgemm_dual<<<dim3(2,128),256,0,st>>>(p_aca+oC, p_win+oC, aca_w, winp_w,
                                             aca_b, winp_b, p_x2+oC);
        ln_kernel<<<NTOK/8,256,0,st>>>(p_x2+oC, g2, b2, p_xn2+oC, NTOK);
        sgemm_kernel<<<dim3(4,128),256,0,st>>>(p_xn2+oC,CDIM, fc1_w,MLPH, fc1_b, nullptr,0,
                                               p_hcat+oH,HF2C, NTOK,MLPH,CDIM, 1);
        tdgather_kernel<<<NTOK*96/256,256,0,st>>>(b*NTOK);
        conv_kernel<<<dim3(17,256),dim3(32,8),0,st>>>(dw_w, dw_b, b);
        sgemm_kernel<<<dim3(2,128),256,0,st>>>(p_hcat2+oH,HF2C, fc2_w,CDIM, fc2_b,
                                               p_x2+oC,CDIM,
                                               (float*)d_out+oC,CDIM, NTOK,CDIM,HF2C, 0);
    }
    // join chains 1-3 back to legacy
    cudaEventRecord(g_eC1, g_s1); cudaStreamWaitEvent(0, g_eC1, 0);
    cudaEventRecord(g_eC2, g_s2); cudaStreamWaitEvent(0, g_eC2, 0);
    cudaEventRecord(g_eC3, g_s3); cudaStreamWaitEvent(0, g_eC3, 0);
}